// round 4
// baseline (speedup 1.0000x reference)
#include <cuda_runtime.h>
#include <cuda_bf16.h>
#include <math.h>

// Problem constants
#define S_MC   4
#define BATCH  128
#define NN     128     // nodes
#define F0     64
#define EMBD   64
#define FIN1   128
#define H1     8
#define F1     16
#define FIN2   128
#define F2     2

#define NTH    512
#define LDS_   132     // padded row stride (floats); 528B keeps float4 rows aligned

// SMEM layout (in floats)
#define OFF_X     0                      // 128*132 = 16896  (x0 -> att e-values)
#define OFF_W     16896                  // 16896            (W1  -> xs2 buffer)
#define OFF_H     33792                  // 16896            (h layer-1)
#define OFF_ASRC  50688                  // 1024  (8 heads * 128)
#define OFF_ADST  51712                  // 1024
#define OFF_ADJ   52736                  // 512 uint32 words
#define OFF_P1S   53248                  // 128 (a_src1[s])
#define OFF_P1D   53376                  // 128 (a_dst1[s])
#define OFF_B1    53504                  // 16
#define OFF_W2    53520                  // 256
#define OFF_H2    53776                  // 256
#define OFF_DST2  54032                  // 128
#define OFF_MISC  54160                  // 16
#define OFF_INV   54176                  // 128 (per-row 1/sum for current head)
#define SMEM_FLOATS 54304
#define SMEM_BYTES (SMEM_FLOATS * 4)     // 217216

typedef unsigned long long ull;

// Packed fp32x2 FMA (Blackwell sm_100+): 2 lane-FMAs per issue slot.
#define FFMA2(d, a, b, c) \
    asm("fma.rn.f32x2 %0, %1, %2, %3;" : "=l"(d) : "l"(a), "l"(b), "l"(c))
#define DUP2(d, s) \
    asm("mov.b64 %0, {%1, %1};" : "=l"(d) : "r"(__float_as_uint(s)))
#define UNPK2(lo, hi, p) \
    asm("mov.b64 {%0, %1}, %2;" : "=f"(lo), "=f"(hi) : "l"(p))

__device__ float g_partial[S_MC * BATCH * F2];   // 1024 floats
__device__ int   g_count;                        // last-CTA election counter

__device__ __forceinline__ float tanh_fast(float x) {
    float y;
    asm("tanh.approx.f32 %0, %1;" : "=f"(y) : "f"(x));
    return y;
}

__device__ __forceinline__ float elu_f(float x) {
    return x > 0.0f ? x : (__expf(x) - 1.0f);
}

__global__ void __launch_bounds__(NTH, 1)
gat_fused_kernel(const float* __restrict__ x,
                 const float* __restrict__ emb,
                 const int*   __restrict__ adj,
                 const float* __restrict__ w1,
                 const float* __restrict__ a_src1,
                 const float* __restrict__ a_dst1,
                 const float* __restrict__ b1,
                 const float* __restrict__ w2,
                 const float* __restrict__ a_src2,
                 const float* __restrict__ a_dst2,
                 const float* __restrict__ b2,
                 float* __restrict__ out)
{
    extern __shared__ float sm[];
    float*    sX    = sm + OFF_X;     // x0, later att e-values
    float*    sW    = sm + OFF_W;     // W1, later xs2
    float*    sH    = sm + OFF_H;     // layer-1 h
    float*    sASRC = sm + OFF_ASRC;
    float*    sADST = sm + OFF_ADST;
    unsigned* sADJ  = (unsigned*)(sm + OFF_ADJ);
    float*    sP1S  = sm + OFF_P1S;
    float*    sP1D  = sm + OFF_P1D;
    float*    sB1   = sm + OFF_B1;
    float*    sW2   = sm + OFF_W2;
    float*    sH2   = sm + OFF_H2;
    float*    sDST2 = sm + OFF_DST2;
    float*    sMISC = sm + OFF_MISC;
    float*    sINV  = sm + OFF_INV;
    __shared__ int sLast;

    const int tid = threadIdx.x;
    const int sb  = blockIdx.x;
    const int s   = sb >> 7;
    const int b   = sb & 127;

    // ---- stage x0 = concat(x[b], emb[b]) : [128][128] ----
    {
        const float4* xv = (const float4*)(x   + (size_t)b * NN * F0);
        const float4* ev = (const float4*)(emb + (size_t)b * NN * EMBD);
        for (int i = tid; i < NN * 32; i += NTH) {      // 4096 float4
            int n = i >> 5, c4 = i & 31;
            float4 v = (c4 < 16) ? xv[n * 16 + c4] : ev[n * 16 + (c4 - 16)];
            *(float4*)&sX[n * LDS_ + c4 * 4] = v;
        }
    }
    // ---- stage W1[s] re-laid as sW[f][head*16+o] ----
    {
        const float4* wv = (const float4*)(w1 + (size_t)s * H1 * FIN1 * F1);
        for (int i = tid; i < 4096; i += NTH) {
            int head = i >> 9;            // 512 float4 per head
            int rem  = i & 511;
            int f = rem >> 2, o4 = rem & 3;
            *(float4*)&sW[f * LDS_ + head * 16 + o4 * 4] = wv[i];
        }
    }
    // ---- small params ----
    if (tid < 128) { sP1S[tid] = a_src1[s * 128 + tid]; sP1D[tid] = a_dst1[s * 128 + tid]; }
    if (tid < 16)  sB1[tid] = b1[tid];
    if (tid < 256) sW2[tid] = w2[s * 256 + tid];
    if (tid == 0) {
        sMISC[0] = a_src2[s * 2 + 0]; sMISC[1] = a_src2[s * 2 + 1];
        sMISC[2] = a_dst2[s * 2 + 0]; sMISC[3] = a_dst2[s * 2 + 1];
        sMISC[4] = b2[0];             sMISC[5] = b2[1];
    }
    // ---- adjacency bitmask: 128 rows * 4 words ----
    {
        int warp = tid >> 5, lane = tid & 31;
        const int* arow = adj + (size_t)b * NN * NN;
        for (int t = warp; t < 512; t += 16) {
            int i = t >> 2, g = t & 3;
            int v = arow[i * NN + g * 32 + lane];
            unsigned bits = __ballot_sync(0xffffffffu, v != 0);
            if (lane == 0) sADJ[t] = bits;
        }
    }
    __syncthreads();

    // ---- GEMM1: h[n][c] = sum_f x0[n][f] * W[f][c]  (128x128x128, FFMA2) ----
    {
        const int tx = tid & 15, ty = tid >> 4;
        const int r0 = ty * 4, c0 = tx * 8;
        ull acc[4][4];
#pragma unroll
        for (int i = 0; i < 4; i++)
#pragma unroll
            for (int p = 0; p < 4; p++) acc[i][p] = 0ULL;

        for (int k = 0; k < 128; k += 4) {
            float4 avec[4];
#pragma unroll
            for (int r = 0; r < 4; r++)
                avec[r] = *(const float4*)&sX[(r0 + r) * LDS_ + k];
#pragma unroll
            for (int kk = 0; kk < 4; kk++) {
                const ulonglong2 b01 = *(const ulonglong2*)&sW[(k + kk) * LDS_ + c0];
                const ulonglong2 b23 = *(const ulonglong2*)&sW[(k + kk) * LDS_ + c0 + 4];
#pragma unroll
                for (int r = 0; r < 4; r++) {
                    const float* af = (const float*)&avec[r];
                    ull ad; DUP2(ad, af[kk]);
                    FFMA2(acc[r][0], ad, b01.x, acc[r][0]);
                    FFMA2(acc[r][1], ad, b01.y, acc[r][1]);
                    FFMA2(acc[r][2], ad, b23.x, acc[r][2]);
                    FFMA2(acc[r][3], ad, b23.y, acc[r][3]);
                }
            }
        }
#pragma unroll
        for (int r = 0; r < 4; r++)
#pragma unroll
            for (int p = 0; p < 4; p++)
                *(ull*)&sH[(r0 + r) * LDS_ + c0 + 2 * p] = acc[r][p];
    }
    __syncthreads();

    // ---- attention projections: att_src/att_dst per (head, n) ----
    for (int id = tid; id < H1 * NN; id += NTH) {
        int head = id >> 7, n = id & 127;
        const float* hrow = sH + n * LDS_ + head * 16;
        float sa = 0.0f, da = 0.0f;
#pragma unroll
        for (int o = 0; o < 16; o++) {
            float t = tanh_fast(hrow[o]);
            sa += t * sP1S[head * 16 + o];
            da += t * sP1D[head * 16 + o];
        }
        sASRC[id] = sa;
        sADST[id] = da;
    }
    __syncthreads();

    // ---- per-head: unnormalized exp into sX + 1/sum, then AV + bias + ELU ----
    for (int head = 0; head < H1; head++) {
        {   // e-rows: 128 rows over 16 warps. Logits are bounded (|v| small),
            // so no max-subtraction is needed; masked lanes contribute 0.
            const int warp = tid >> 5, lane = tid & 31;
#pragma unroll
            for (int it = 0; it < 8; it++) {
                const int i = warp + it * 16;
                float src = sASRC[head * 128 + i];
                float e[4], sum = 0.0f;
#pragma unroll
                for (int g = 0; g < 4; g++) {
                    int j = g * 32 + lane;
                    float v = src + sADST[head * 128 + j];
                    v = fmaxf(v, 0.2f * v);                    // leaky_relu 0.2
                    unsigned bits = sADJ[i * 4 + g];
                    float ev = ((bits >> lane) & 1u) ? __expf(v) : 0.0f;
                    e[g] = ev; sum += ev;
                }
#pragma unroll
                for (int d = 16; d > 0; d >>= 1) sum += __shfl_xor_sync(0xffffffffu, sum, d);
#pragma unroll
                for (int g = 0; g < 4; g++)
                    sX[i * LDS_ + g * 32 + lane] = e[g];
                if (lane == 0) sINV[i] = 1.0f / sum;
            }
        }
        __syncthreads();
        {   // AV on all 512 threads: 1 row x 4 cols per thread, FFMA2
            const int cg = tid & 3;
            const int i  = tid >> 2;
            const int c  = head * 16 + cg * 4;
            ull a0 = 0ULL, a1 = 0ULL;
            const float* arow = sX + i * LDS_;
            for (int j = 0; j < 128; j += 4) {
                float4 av = *(const float4*)&arow[j];
                const float* af = (const float*)&av;
#pragma unroll
                for (int jj = 0; jj < 4; jj++) {
                    const ulonglong2 hv = *(const ulonglong2*)&sH[(j + jj) * LDS_ + c];
                    ull d; DUP2(d, af[jj]);
                    FFMA2(a0, d, hv.x, a0);
                    FFMA2(a1, d, hv.y, a1);
                }
            }
            const float inv = sINV[i];
            const int cl = cg * 4;
            float v0, v1, v2, v3;
            UNPK2(v0, v1, a0); UNPK2(v2, v3, a1);
            float4 o0;
            o0.x = elu_f(v0 * inv + sB1[cl + 0]);
            o0.y = elu_f(v1 * inv + sB1[cl + 1]);
            o0.z = elu_f(v2 * inv + sB1[cl + 2]);
            o0.w = elu_f(v3 * inv + sB1[cl + 3]);
            *(float4*)&sW[i * LDS_ + c] = o0;       // xs2 layout [n][h*16+o]
        }
        __syncthreads();
    }

    // ---- layer 2 linear: h2[n][0:2] = sum_f xs2[n][f] * w2[f][0:2]  (FFMA2) ----
    if (tid < 128) {
        const int n = tid;
        const float* xr = sW + n * LDS_;
        const ull* w2p = (const ull*)sW2;          // w2[f][0:2] packed pairs
        ull acc = 0ULL;
        for (int f = 0; f < 128; f += 4) {
            float4 xv = *(const float4*)&xr[f];
            const float* xf = (const float*)&xv;
#pragma unroll
            for (int ff = 0; ff < 4; ff++) {
                ull d; DUP2(d, xf[ff]);
                FFMA2(acc, d, w2p[f + ff], acc);
            }
        }
        *(ull*)&sH2[2 * n] = acc;
    }
    __syncthreads();
    if (tid < 128) {
        int n = tid;
        float t0 = tanh_fast(sH2[2 * n]);
        float t1 = tanh_fast(sH2[2 * n + 1]);
        sDST2[n] = t0 * sMISC[2] + t1 * sMISC[3];
        if (n == 127) sMISC[6] = t0 * sMISC[0] + t1 * sMISC[1];  // src at ego node
    }
    __syncthreads();

    // ---- ego-node attention row (i = 127), softmax, AV, log_softmax ----
    if (tid < 32) {
        int lane = tid;
        float src = sMISC[6];
        float l[4];
#pragma unroll
        for (int g = 0; g < 4; g++) {
            int j = g * 32 + lane;
            float v = src + sDST2[j];
            v = fmaxf(v, 0.2f * v);
            unsigned bits = sADJ[127 * 4 + g];
            l[g] = ((bits >> lane) & 1u) ? v : -1e9f;
        }
        float m = fmaxf(fmaxf(l[0], l[1]), fmaxf(l[2], l[3]));
#pragma unroll
        for (int d = 16; d > 0; d >>= 1) m = fmaxf(m, __shfl_xor_sync(0xffffffffu, m, d));
        float sum = 0.0f, a0 = 0.0f, a1 = 0.0f;
#pragma unroll
        for (int g = 0; g < 4; g++) {
            int j = g * 32 + lane;
            float e = __expf(l[g] - m);
            sum += e;
            a0 += e * sH2[2 * j];
            a1 += e * sH2[2 * j + 1];
        }
#pragma unroll
        for (int d = 16; d > 0; d >>= 1) {
            sum += __shfl_xor_sync(0xffffffffu, sum, d);
            a0  += __shfl_xor_sync(0xffffffffu, a0, d);
            a1  += __shfl_xor_sync(0xffffffffu, a1, d);
        }
        if (lane == 0) {
            float inv = 1.0f / sum;
            float o0 = a0 * inv + sMISC[4];
            float o1 = a1 * inv + sMISC[5];
            float mm  = fmaxf(o0, o1);
            float lse = mm + logf(expf(o0 - mm) + expf(o1 - mm));
            g_partial[(s * BATCH + b) * 2 + 0] = o0 - lse;
            g_partial[(s * BATCH + b) * 2 + 1] = o1 - lse;
        }
    }

    // ---- last-CTA final reduce (mean over S) ----
    if (tid == 0) {
        __threadfence();
        int old = atomicAdd(&g_count, 1);
        sLast = (old == (S_MC * BATCH - 1)) ? 1 : 0;
    }
    __syncthreads();
    if (sLast) {
        if (tid < 256) {
            const volatile float* gp = g_partial;
            float v = gp[tid] + gp[256 + tid] + gp[512 + tid] + gp[768 + tid];
            out[tid] = 0.25f * v;
        }
        if (tid == 0) g_count = 0;    // reset for next (deterministic) call
    }
}

extern "C" void kernel_launch(void* const* d_in, const int* in_sizes, int n_in,
                              void* d_out, int out_size)
{
    const float* x      = (const float*)d_in[0];
    const float* emb    = (const float*)d_in[1];
    const int*   adj    = (const int*)d_in[2];
    const float* w1     = (const float*)d_in[3];
    const float* a_src1 = (const float*)d_in[4];
    const float* a_dst1 = (const float*)d_in[5];
    const float* b1     = (const float*)d_in[6];
    const float* w2     = (const float*)d_in[7];
    const float* a_src2 = (const float*)d_in[8];
    const float* a_dst2 = (const float*)d_in[9];
    const float* b2     = (const float*)d_in[10];

    cudaFuncSetAttribute(gat_fused_kernel,
                         cudaFuncAttributeMaxDynamicSharedMemorySize, SMEM_BYTES);

    gat_fused_kernel<<<S_MC * BATCH, NTH, SMEM_BYTES>>>(
        x, emb, adj, w1, a_src1, a_dst1, b1, w2, a_src2, a_dst2, b2,
        (float*)d_out);
}

// round 5
// speedup vs baseline: 1.0872x; 1.0872x over previous
#include <cuda_runtime.h>
#include <cuda_bf16.h>
#include <math.h>

// Problem constants
#define S_MC   4
#define BATCH  128
#define NN     128
#define F0     64
#define EMBD   64
#define FIN1   128
#define H1     8
#define F1     16
#define FIN2   128
#define F2     2

#define NTH    1024
#define LDS_   132     // padded row stride (floats); 528B keeps 16B alignment

// SMEM layout (floats)
#define OFF_X     0                      // 16896: x0, later att e-values (row-major [i][j])
#define OFF_W     16896                  // 16896: W1^T [c][f], later xs2 [n][c]
#define OFF_H     33792                  // 16896: h^T  [c][n]
#define OFF_ASRC  50688                  // 1024
#define OFF_ADST  51712                  // 1024
#define OFF_ED    52736                  // 1024  exp(dst)
#define OFF_ED2   53760                  // 1024  exp(0.2*dst)
#define OFF_ADJ   54784                  // 512 uint32 words
#define OFF_P1S   55296                  // 128
#define OFF_P1D   55424                  // 128
#define OFF_B1    55552                  // 16
#define OFF_W2T   55568                  // 256  w2^T [o][f]
#define OFF_H2    55824                  // 256
#define OFF_DST2  56080                  // 128
#define OFF_MISC  56208                  // 16
#define OFF_INV   56224                  // 128
#define SMEM_FLOATS 56352
#define SMEM_BYTES (SMEM_FLOATS * 4)     // 225408

typedef unsigned long long ull;

#define FFMA2(d, a, b, c) \
    asm("fma.rn.f32x2 %0, %1, %2, %3;" : "=l"(d) : "l"(a), "l"(b), "l"(c))
#define UNPK2(lo, hi, p) \
    asm("mov.b64 {%0, %1}, %2;" : "=f"(lo), "=f"(hi) : "l"(p))
#define PACK2(d, lo, hi) \
    asm("mov.b64 %0, {%1, %2};" : "=l"(d) : "f"(lo), "f"(hi))

__device__ float g_partial[S_MC * BATCH * F2];
__device__ int   g_count;

__device__ __forceinline__ float tanh_fast(float x) {
    float y;
    asm("tanh.approx.f32 %0, %1;" : "=f"(y) : "f"(x));
    return y;
}
__device__ __forceinline__ float elu_f(float x) {
    return x > 0.0f ? x : (__expf(x) - 1.0f);
}

__global__ void __launch_bounds__(NTH, 1)
gat_fused_kernel(const float* __restrict__ x,
                 const float* __restrict__ emb,
                 const int*   __restrict__ adj,
                 const float* __restrict__ w1,
                 const float* __restrict__ a_src1,
                 const float* __restrict__ a_dst1,
                 const float* __restrict__ b1,
                 const float* __restrict__ w2,
                 const float* __restrict__ a_src2,
                 const float* __restrict__ a_dst2,
                 const float* __restrict__ b2,
                 float* __restrict__ out)
{
    extern __shared__ float sm[];
    float*    sX    = sm + OFF_X;     // x0 -> att e-values
    float*    sW    = sm + OFF_W;     // W1^T -> xs2
    float*    sHT   = sm + OFF_H;     // h^T [c][n]
    float*    sASRC = sm + OFF_ASRC;
    float*    sADST = sm + OFF_ADST;
    float*    sED   = sm + OFF_ED;
    float*    sED2  = sm + OFF_ED2;
    unsigned* sADJ  = (unsigned*)(sm + OFF_ADJ);
    float*    sP1S  = sm + OFF_P1S;
    float*    sP1D  = sm + OFF_P1D;
    float*    sB1   = sm + OFF_B1;
    float*    sW2T  = sm + OFF_W2T;
    float*    sH2   = sm + OFF_H2;
    float*    sDST2 = sm + OFF_DST2;
    float*    sMISC = sm + OFF_MISC;
    float*    sINV  = sm + OFF_INV;
    __shared__ int sLast;

    const int tid = threadIdx.x;
    const int sb  = blockIdx.x;
    const int s   = sb >> 7;
    const int b   = sb & 127;
    const int warp = tid >> 5, lane = tid & 31;

    // ---- stage x0 = concat(x[b], emb[b]) : [128][128] ----
    {
        const float4* xv = (const float4*)(x   + (size_t)b * NN * F0);
        const float4* ev = (const float4*)(emb + (size_t)b * NN * EMBD);
        for (int i = tid; i < NN * 32; i += NTH) {
            int n = i >> 5, c4 = i & 31;
            float4 v = (c4 < 16) ? xv[n * 16 + c4] : ev[n * 16 + (c4 - 16)];
            *(float4*)&sX[n * LDS_ + c4 * 4] = v;
        }
    }
    // ---- stage W1[s] transposed: sW[c][f], c = head*16+o ----
    {
        const float4* wv = (const float4*)(w1 + (size_t)s * H1 * FIN1 * F1);
        for (int i = tid; i < 4096; i += NTH) {
            int head = i >> 9;
            int rem  = i & 511;
            int f = rem >> 2, o4 = rem & 3;
            float4 v = wv[i];
            int c = head * 16 + o4 * 4;
            sW[(c + 0) * LDS_ + f] = v.x;
            sW[(c + 1) * LDS_ + f] = v.y;
            sW[(c + 2) * LDS_ + f] = v.z;
            sW[(c + 3) * LDS_ + f] = v.w;
        }
    }
    // ---- small params ----
    if (tid < 128) { sP1S[tid] = a_src1[s * 128 + tid]; sP1D[tid] = a_dst1[s * 128 + tid]; }
    if (tid < 16)  sB1[tid] = b1[tid];
    if (tid < 256) { int f = tid >> 1, o = tid & 1; sW2T[o * 128 + f] = w2[s * 256 + tid]; }
    if (tid == 0) {
        sMISC[0] = a_src2[s * 2 + 0]; sMISC[1] = a_src2[s * 2 + 1];
        sMISC[2] = a_dst2[s * 2 + 0]; sMISC[3] = a_dst2[s * 2 + 1];
        sMISC[4] = b2[0];             sMISC[5] = b2[1];
    }
    // ---- adjacency bitmask: 128 rows * 4 words ----
    {
        const int* arow = adj + (size_t)b * NN * NN;
        for (int t = warp; t < 512; t += 32) {
            int i = t >> 2, g = t & 3;
            int v = arow[i * NN + g * 32 + lane];
            unsigned bits = __ballot_sync(0xffffffffu, v != 0);
            if (lane == 0) sADJ[t] = bits;
        }
    }
    __syncthreads();

    // ---- GEMM1: hT[c][n] = sum_f x0[n][f] * wT[c][f]  (pair-over-f f32x2) ----
    {
        const int ct = tid & 63, rt = tid >> 6;
        const int c0 = ct * 2, r0 = rt * 8;
        ull acc[8][2];
#pragma unroll
        for (int r = 0; r < 8; r++) { acc[r][0] = 0ULL; acc[r][1] = 0ULL; }

        for (int f = 0; f < 128; f += 4) {
            const ulonglong2 b0 = *(const ulonglong2*)&sW[(c0 + 0) * LDS_ + f];
            const ulonglong2 b1v = *(const ulonglong2*)&sW[(c0 + 1) * LDS_ + f];
#pragma unroll
            for (int r = 0; r < 8; r++) {
                const ulonglong2 ap = *(const ulonglong2*)&sX[(r0 + r) * LDS_ + f];
                FFMA2(acc[r][0], ap.x, b0.x, acc[r][0]);
                FFMA2(acc[r][0], ap.y, b0.y, acc[r][0]);
                FFMA2(acc[r][1], ap.x, b1v.x, acc[r][1]);
                FFMA2(acc[r][1], ap.y, b1v.y, acc[r][1]);
            }
        }
#pragma unroll
        for (int r = 0; r < 8; r++)
#pragma unroll
            for (int cc = 0; cc < 2; cc++) {
                float lo, hi;
                UNPK2(lo, hi, acc[r][cc]);
                sHT[(c0 + cc) * LDS_ + r0 + r] = lo + hi;
            }
    }
    __syncthreads();

    // ---- att projections + exp factors per (head, n) ----
    {
        const int head = tid >> 7, n = tid & 127;
        const float* hcol = sHT + (head * 16) * LDS_ + n;
        float sa = 0.0f, da = 0.0f;
#pragma unroll
        for (int o = 0; o < 16; o++) {
            float t = tanh_fast(hcol[o * LDS_]);
            sa += t * sP1S[head * 16 + o];
            da += t * sP1D[head * 16 + o];
        }
        sASRC[tid] = sa;
        sADST[tid] = da;
        sED[tid]   = __expf(da);
        sED2[tid]  = __expf(0.2f * da);
    }
    __syncthreads();

    // ---- per-head: e-values (factorized exp) into sX, then AV + bias + ELU ----
    for (int head = 0; head < H1; head++) {
        {   // 32 warps x 4 rows; lane owns j = lane*4..lane*4+4 (loop-invariant dst data)
            const int j0 = lane * 4;
            const float4 dstv = *(const float4*)&sADST[head * 128 + j0];
            const float4 edv  = *(const float4*)&sED[head * 128 + j0];
            const float4 ed2v = *(const float4*)&sED2[head * 128 + j0];
            const float* df  = (const float*)&dstv;
            const float* ef  = (const float*)&edv;
            const float* e2f = (const float*)&ed2v;
            const int wsh = (lane & 7) * 4;   // bit base within adj word
#pragma unroll
            for (int it = 0; it < 4; it++) {
                const int i = warp + it * 32;
                const float src = sASRC[head * 128 + i];
                const float Ei  = __expf(src);          // uniform across warp: 1 MUFU instr
                const float Ei2 = __expf(0.2f * src);
                const unsigned wbits = sADJ[i * 4 + (lane >> 3)];
                float e[4];
                float sum = 0.0f;
#pragma unroll
                for (int jj = 0; jj < 4; jj++) {
                    float v  = src + df[jj];
                    float ep = (v > 0.0f) ? (Ei * ef[jj]) : (Ei2 * e2f[jj]);
                    ep = ((wbits >> (wsh + jj)) & 1u) ? ep : 0.0f;
                    e[jj] = ep; sum += ep;
                }
#pragma unroll
                for (int d = 16; d > 0; d >>= 1) sum += __shfl_xor_sync(0xffffffffu, sum, d);
                *(float4*)&sX[i * LDS_ + j0] = make_float4(e[0], e[1], e[2], e[3]);
                if (lane == 0) sINV[i] = 1.0f / sum;
            }
        }
        __syncthreads();
        if (tid < 512) {   // AV: 2 rows x 2 cols per thread, pair-over-j f32x2
            const int cg = tid & 7;
            const int i2 = tid >> 3;
            const int r0 = i2 * 2;
            const int c  = head * 16 + cg * 2;
            ull a00 = 0ULL, a01 = 0ULL, a10 = 0ULL, a11 = 0ULL;
            const float* ar0 = sX + r0 * LDS_;
            const float* ar1 = ar0 + LDS_;
            const float* h0  = sHT + (c + 0) * LDS_;
            const float* h1  = sHT + (c + 1) * LDS_;
            for (int j = 0; j < 128; j += 4) {
                const ulonglong2 ap0 = *(const ulonglong2*)&ar0[j];
                const ulonglong2 ap1 = *(const ulonglong2*)&ar1[j];
                const ulonglong2 hp0 = *(const ulonglong2*)&h0[j];
                const ulonglong2 hp1 = *(const ulonglong2*)&h1[j];
                FFMA2(a00, ap0.x, hp0.x, a00);
                FFMA2(a00, ap0.y, hp0.y, a00);
                FFMA2(a01, ap0.x, hp1.x, a01);
                FFMA2(a01, ap0.y, hp1.y, a01);
                FFMA2(a10, ap1.x, hp0.x, a10);
                FFMA2(a10, ap1.y, hp0.y, a10);
                FFMA2(a11, ap1.x, hp1.x, a11);
                FFMA2(a11, ap1.y, hp1.y, a11);
            }
            const float inv0 = sINV[r0], inv1 = sINV[r0 + 1];
            const float bb0 = sB1[cg * 2], bb1 = sB1[cg * 2 + 1];
            float lo, hi, u0, u1;
            UNPK2(lo, hi, a00); u0 = elu_f((lo + hi) * inv0 + bb0);
            UNPK2(lo, hi, a01); u1 = elu_f((lo + hi) * inv0 + bb1);
            ull pk; PACK2(pk, u0, u1);
            *(ull*)&sW[r0 * LDS_ + c] = pk;
            UNPK2(lo, hi, a10); u0 = elu_f((lo + hi) * inv1 + bb0);
            UNPK2(lo, hi, a11); u1 = elu_f((lo + hi) * inv1 + bb1);
            PACK2(pk, u0, u1);
            *(ull*)&sW[(r0 + 1) * LDS_ + c] = pk;
        }
        __syncthreads();
    }

    // ---- layer 2 linear: h2[n][0:2], f split 8 ways + shfl reduce ----
    {
        const int n = tid >> 3, fs = tid & 7;
        const float* xr = sW + n * LDS_ + fs * 16;
        const ull* w2o0 = (const ull*)&sW2T[0 * 128 + fs * 16];
        const ull* w2o1 = (const ull*)&sW2T[1 * 128 + fs * 16];
        ull acc0 = 0ULL, acc1 = 0ULL;
#pragma unroll
        for (int fp = 0; fp < 8; fp++) {
            const ull xp = *(const ull*)&xr[fp * 2];
            FFMA2(acc0, xp, w2o0[fp], acc0);
            FFMA2(acc1, xp, w2o1[fp], acc1);
        }
        float l0, h0, l1, h1;
        UNPK2(l0, h0, acc0); UNPK2(l1, h1, acc1);
        float p0 = l0 + h0, p1 = l1 + h1;
#pragma unroll
        for (int d = 4; d > 0; d >>= 1) {
            p0 += __shfl_xor_sync(0xffffffffu, p0, d);
            p1 += __shfl_xor_sync(0xffffffffu, p1, d);
        }
        if (fs == 0) { sH2[2 * n] = p0; sH2[2 * n + 1] = p1; }
    }
    __syncthreads();
    if (tid < 128) {
        int n = tid;
        float t0 = tanh_fast(sH2[2 * n]);
        float t1 = tanh_fast(sH2[2 * n + 1]);
        sDST2[n] = t0 * sMISC[2] + t1 * sMISC[3];
        if (n == 127) sMISC[6] = t0 * sMISC[0] + t1 * sMISC[1];
    }
    __syncthreads();

    // ---- ego-node attention row (i = 127), softmax, AV, log_softmax ----
    if (tid < 32) {
        float src = sMISC[6];
        float l[4];
#pragma unroll
        for (int g = 0; g < 4; g++) {
            int j = g * 32 + lane;
            float v = src + sDST2[j];
            v = fmaxf(v, 0.2f * v);
            unsigned bits = sADJ[127 * 4 + g];
            l[g] = ((bits >> lane) & 1u) ? v : -1e9f;
        }
        float m = fmaxf(fmaxf(l[0], l[1]), fmaxf(l[2], l[3]));
#pragma unroll
        for (int d = 16; d > 0; d >>= 1) m = fmaxf(m, __shfl_xor_sync(0xffffffffu, m, d));
        float sum = 0.0f, a0 = 0.0f, a1 = 0.0f;
#pragma unroll
        for (int g = 0; g < 4; g++) {
            int j = g * 32 + lane;
            float e = __expf(l[g] - m);
            sum += e;
            a0 += e * sH2[2 * j];
            a1 += e * sH2[2 * j + 1];
        }
#pragma unroll
        for (int d = 16; d > 0; d >>= 1) {
            sum += __shfl_xor_sync(0xffffffffu, sum, d);
            a0  += __shfl_xor_sync(0xffffffffu, a0, d);
            a1  += __shfl_xor_sync(0xffffffffu, a1, d);
        }
        if (lane == 0) {
            float inv = 1.0f / sum;
            float o0 = a0 * inv + sMISC[4];
            float o1 = a1 * inv + sMISC[5];
            float mm  = fmaxf(o0, o1);
            float lse = mm + logf(expf(o0 - mm) + expf(o1 - mm));
            g_partial[(s * BATCH + b) * 2 + 0] = o0 - lse;
            g_partial[(s * BATCH + b) * 2 + 1] = o1 - lse;
        }
    }

    // ---- last-CTA final reduce (mean over S) ----
    if (tid == 0) {
        __threadfence();
        int old = atomicAdd(&g_count, 1);
        sLast = (old == (S_MC * BATCH - 1)) ? 1 : 0;
    }
    __syncthreads();
    if (sLast) {
        if (tid < 256) {
            const volatile float* gp = g_partial;
            float v = gp[tid] + gp[256 + tid] + gp[512 + tid] + gp[768 + tid];
            out[tid] = 0.25f * v;
        }
        if (tid == 0) g_count = 0;
    }
}

extern "C" void kernel_launch(void* const* d_in, const int* in_sizes, int n_in,
                              void* d_out, int out_size)
{
    const float* x      = (const float*)d_in[0];
    const float* emb    = (const float*)d_in[1];
    const int*   adj    = (const int*)d_in[2];
    const float* w1     = (const float*)d_in[3];
    const float* a_src1 = (const float*)d_in[4];
    const float* a_dst1 = (const float*)d_in[5];
    const float* b1     = (const float*)d_in[6];
    const float* w2     = (const float*)d_in[7];
    const float* a_src2 = (const float*)d_in[8];
    const float* a_dst2 = (const float*)d_in[9];
    const float* b2     = (const float*)d_in[10];

    cudaFuncSetAttribute(gat_fused_kernel,
                         cudaFuncAttributeMaxDynamicSharedMemorySize, SMEM_BYTES);

    gat_fused_kernel<<<S_MC * BATCH, NTH, SMEM_BYTES>>>(
        x, emb, adj, w1, a_src1, a_dst1, b1, w2, a_src2, a_dst2, b2,
        (float*)d_out);
}

// round 6
// speedup vs baseline: 1.4077x; 1.2948x over previous
#include <cuda_runtime.h>
#include <cuda_bf16.h>
#include <math.h>

// Problem constants
#define S_MC   4
#define BATCH  128
#define NN     128
#define F0     64
#define EMBD   64
#define FIN1   128
#define H1     8
#define F1     16
#define FIN2   128
#define F2     2

#define NTH    1024
#define LDS_   132     // padded row stride (floats); 132 ≡ 4 (mod 32) banks:
                       // consecutive ROWS hit consecutive bank-quads -> conflict-free
                       // 16B row-stepped access when lanes step 1 row.

// SMEM layout (floats)
#define OFF_X     0                      // 16896: x0, later att e-values (row-major [i][j])
#define OFF_W     16896                  // 16896: W1^T [c][f], later xs2 [n][c]
#define OFF_H     33792                  // 16896: h^T  [c][n]
#define OFF_ASRC  50688                  // 1024
#define OFF_ADST  51712                  // 1024
#define OFF_ED    52736                  // 1024  exp(dst)
#define OFF_ED2   53760                  // 1024  exp(0.2*dst)
#define OFF_ADJ   54784                  // 512 uint32 words
#define OFF_P1S   55296                  // 128
#define OFF_P1D   55424                  // 128
#define OFF_B1    55552                  // 16
#define OFF_W2T   55568                  // 256  w2^T [o][f]
#define OFF_H2    55824                  // 256
#define OFF_DST2  56080                  // 128
#define OFF_MISC  56208                  // 16
#define OFF_INV   56224                  // 128
#define SMEM_FLOATS 56352
#define SMEM_BYTES (SMEM_FLOATS * 4)     // 225408

typedef unsigned long long ull;

#define FFMA2(d, a, b, c) \
    asm("fma.rn.f32x2 %0, %1, %2, %3;" : "=l"(d) : "l"(a), "l"(b), "l"(c))
#define UNPK2(lo, hi, p) \
    asm("mov.b64 {%0, %1}, %2;" : "=f"(lo), "=f"(hi) : "l"(p))

__device__ float g_partial[S_MC * BATCH * F2];
__device__ int   g_count;

__device__ __forceinline__ float tanh_fast(float x) {
    float y;
    asm("tanh.approx.f32 %0, %1;" : "=f"(y) : "f"(x));
    return y;
}
__device__ __forceinline__ float elu_f(float x) {
    return x > 0.0f ? x : (__expf(x) - 1.0f);
}

__global__ void __launch_bounds__(NTH, 1)
gat_fused_kernel(const float* __restrict__ x,
                 const float* __restrict__ emb,
                 const int*   __restrict__ adj,
                 const float* __restrict__ w1,
                 const float* __restrict__ a_src1,
                 const float* __restrict__ a_dst1,
                 const float* __restrict__ b1,
                 const float* __restrict__ w2,
                 const float* __restrict__ a_src2,
                 const float* __restrict__ a_dst2,
                 const float* __restrict__ b2,
                 float* __restrict__ out)
{
    extern __shared__ float sm[];
    float*    sX    = sm + OFF_X;     // x0 -> att e-values
    float*    sW    = sm + OFF_W;     // W1^T -> xs2
    float*    sHT   = sm + OFF_H;     // h^T [c][n]
    float*    sASRC = sm + OFF_ASRC;
    float*    sADST = sm + OFF_ADST;
    float*    sED   = sm + OFF_ED;
    float*    sED2  = sm + OFF_ED2;
    unsigned* sADJ  = (unsigned*)(sm + OFF_ADJ);
    float*    sP1S  = sm + OFF_P1S;
    float*    sP1D  = sm + OFF_P1D;
    float*    sB1   = sm + OFF_B1;
    float*    sW2T  = sm + OFF_W2T;
    float*    sH2   = sm + OFF_H2;
    float*    sDST2 = sm + OFF_DST2;
    float*    sMISC = sm + OFF_MISC;
    float*    sINV  = sm + OFF_INV;
    __shared__ int sLast;

    const int tid = threadIdx.x;
    const int sb  = blockIdx.x;
    const int s   = sb >> 7;
    const int b   = sb & 127;
    const int warp = tid >> 5, lane = tid & 31;

    // ---- stage x0 = concat(x[b], emb[b]) : [128][128] ----
    {
        const float4* xv = (const float4*)(x   + (size_t)b * NN * F0);
        const float4* ev = (const float4*)(emb + (size_t)b * NN * EMBD);
        for (int i = tid; i < NN * 32; i += NTH) {
            int n = i >> 5, c4 = i & 31;
            float4 v = (c4 < 16) ? xv[n * 16 + c4] : ev[n * 16 + (c4 - 16)];
            *(float4*)&sX[n * LDS_ + c4 * 4] = v;
        }
    }
    // ---- stage W1[s] transposed: sW[c][f], c = head*16+o ----
    {
        const float4* wv = (const float4*)(w1 + (size_t)s * H1 * FIN1 * F1);
        for (int i = tid; i < 4096; i += NTH) {
            int head = i >> 9;
            int rem  = i & 511;
            int f = rem >> 2, o4 = rem & 3;
            float4 v = wv[i];
            int c = head * 16 + o4 * 4;
            sW[(c + 0) * LDS_ + f] = v.x;
            sW[(c + 1) * LDS_ + f] = v.y;
            sW[(c + 2) * LDS_ + f] = v.z;
            sW[(c + 3) * LDS_ + f] = v.w;
        }
    }
    // ---- small params ----
    if (tid < 128) { sP1S[tid] = a_src1[s * 128 + tid]; sP1D[tid] = a_dst1[s * 128 + tid]; }
    if (tid < 16)  sB1[tid] = b1[tid];
    if (tid < 256) { int f = tid >> 1, o = tid & 1; sW2T[o * 128 + f] = w2[s * 256 + tid]; }
    if (tid == 0) {
        sMISC[0] = a_src2[s * 2 + 0]; sMISC[1] = a_src2[s * 2 + 1];
        sMISC[2] = a_dst2[s * 2 + 0]; sMISC[3] = a_dst2[s * 2 + 1];
        sMISC[4] = b2[0];             sMISC[5] = b2[1];
    }
    // ---- adjacency bitmask: 128 rows * 4 words ----
    {
        const int* arow = adj + (size_t)b * NN * NN;
        for (int t = warp; t < 512; t += 32) {
            int i = t >> 2, g = t & 3;
            int v = arow[i * NN + g * 32 + lane];
            unsigned bits = __ballot_sync(0xffffffffu, v != 0);
            if (lane == 0) sADJ[t] = bits;
        }
    }
    __syncthreads();

    // ---- GEMM1: hT[c][n] = sum_f x0[n][f] * wT[c][f] ----
    // Thread owns cols {ct, ct+64} (lane-consecutive -> conflict-free B loads)
    // and rows r0..r0+7 (warp-uniform -> broadcast A loads).
    {
        const int ct = tid & 63, rt = tid >> 6;
        const int c0 = ct, c1 = ct + 64;
        const int r0 = rt * 8;
        ull acc0[8], acc1[8];
#pragma unroll
        for (int r = 0; r < 8; r++) { acc0[r] = 0ULL; acc1[r] = 0ULL; }

        const float* w0 = sW + c0 * LDS_;
        const float* w1r = sW + c1 * LDS_;
        for (int f = 0; f < 128; f += 4) {
            const ulonglong2 b0 = *(const ulonglong2*)&w0[f];
            const ulonglong2 b1v = *(const ulonglong2*)&w1r[f];
#pragma unroll
            for (int r = 0; r < 8; r++) {
                const ulonglong2 ap = *(const ulonglong2*)&sX[(r0 + r) * LDS_ + f];
                FFMA2(acc0[r], ap.x, b0.x, acc0[r]);
                FFMA2(acc0[r], ap.y, b0.y, acc0[r]);
                FFMA2(acc1[r], ap.x, b1v.x, acc1[r]);
                FFMA2(acc1[r], ap.y, b1v.y, acc1[r]);
            }
        }
        float v0[8], v1[8];
#pragma unroll
        for (int r = 0; r < 8; r++) {
            float lo, hi;
            UNPK2(lo, hi, acc0[r]); v0[r] = lo + hi;
            UNPK2(lo, hi, acc1[r]); v1[r] = lo + hi;
        }
        *(float4*)&sHT[c0 * LDS_ + r0]     = make_float4(v0[0], v0[1], v0[2], v0[3]);
        *(float4*)&sHT[c0 * LDS_ + r0 + 4] = make_float4(v0[4], v0[5], v0[6], v0[7]);
        *(float4*)&sHT[c1 * LDS_ + r0]     = make_float4(v1[0], v1[1], v1[2], v1[3]);
        *(float4*)&sHT[c1 * LDS_ + r0 + 4] = make_float4(v1[4], v1[5], v1[6], v1[7]);
    }
    __syncthreads();

    // ---- att projections + exp factors per (head, n) ----
    {
        const int head = tid >> 7, n = tid & 127;
        const float* hcol = sHT + (head * 16) * LDS_ + n;
        float sa = 0.0f, da = 0.0f;
#pragma unroll
        for (int o = 0; o < 16; o++) {
            float t = tanh_fast(hcol[o * LDS_]);
            sa += t * sP1S[head * 16 + o];
            da += t * sP1D[head * 16 + o];
        }
        sASRC[tid] = sa;
        sADST[tid] = da;
        sED[tid]   = __expf(da);
        sED2[tid]  = __expf(0.2f * da);
    }
    __syncthreads();

    // ---- per-head: e-values (factorized exp) into sX, then AV + bias + ELU ----
    for (int head = 0; head < H1; head++) {
        {   // 32 warps x 4 rows; lane owns j = lane*4..+4 (loop-invariant dst data)
            const int j0 = lane * 4;
            const float4 dstv = *(const float4*)&sADST[head * 128 + j0];
            const float4 edv  = *(const float4*)&sED[head * 128 + j0];
            const float4 ed2v = *(const float4*)&sED2[head * 128 + j0];
            const float* df  = (const float*)&dstv;
            const float* ef  = (const float*)&edv;
            const float* e2f = (const float*)&ed2v;
            const int wsh = (lane & 7) * 4;
#pragma unroll
            for (int it = 0; it < 4; it++) {
                const int i = warp + it * 32;
                const float src = sASRC[head * 128 + i];
                const float Ei  = __expf(src);
                const float Ei2 = __expf(0.2f * src);
                const unsigned wbits = sADJ[i * 4 + (lane >> 3)];
                float e[4];
                float sum = 0.0f;
#pragma unroll
                for (int jj = 0; jj < 4; jj++) {
                    float v  = src + df[jj];
                    float ep = (v > 0.0f) ? (Ei * ef[jj]) : (Ei2 * e2f[jj]);
                    ep = ((wbits >> (wsh + jj)) & 1u) ? ep : 0.0f;
                    e[jj] = ep; sum += ep;
                }
#pragma unroll
                for (int d = 16; d > 0; d >>= 1) sum += __shfl_xor_sync(0xffffffffu, sum, d);
                *(float4*)&sX[i * LDS_ + j0] = make_float4(e[0], e[1], e[2], e[3]);
                if (lane == 0) sINV[i] = 1.0f / sum;
            }
        }
        __syncthreads();
        if (tid < 512) {
            // AV: 2 rows x cols {cg, cg+8}; cg lane-consecutive -> conflict-free
            // h loads (broadcast over the 4 row-groups); e rows cover quads 0-7.
            const int cg = tid & 7;
            const int i2 = tid >> 3;
            const int r0 = 2 * i2;
            const int ca = head * 16 + cg, cb = ca + 8;
            ull a00 = 0ULL, a01 = 0ULL, a10 = 0ULL, a11 = 0ULL;
            const float* ar0 = sX + r0 * LDS_;
            const float* ar1 = ar0 + LDS_;
            const float* ha  = sHT + ca * LDS_;
            const float* hb  = sHT + cb * LDS_;
            for (int j = 0; j < 128; j += 4) {
                const ulonglong2 ap0 = *(const ulonglong2*)&ar0[j];
                const ulonglong2 ap1 = *(const ulonglong2*)&ar1[j];
                const ulonglong2 hpa = *(const ulonglong2*)&ha[j];
                const ulonglong2 hpb = *(const ulonglong2*)&hb[j];
                FFMA2(a00, ap0.x, hpa.x, a00);
                FFMA2(a00, ap0.y, hpa.y, a00);
                FFMA2(a01, ap0.x, hpb.x, a01);
                FFMA2(a01, ap0.y, hpb.y, a01);
                FFMA2(a10, ap1.x, hpa.x, a10);
                FFMA2(a10, ap1.y, hpa.y, a10);
                FFMA2(a11, ap1.x, hpb.x, a11);
                FFMA2(a11, ap1.y, hpb.y, a11);
            }
            const float inv0 = sINV[r0], inv1 = sINV[r0 + 1];
            const float ba = sB1[cg], bb = sB1[cg + 8];
            float lo, hi;
            UNPK2(lo, hi, a00); sW[r0 * LDS_ + ca]       = elu_f((lo + hi) * inv0 + ba);
            UNPK2(lo, hi, a01); sW[r0 * LDS_ + cb]       = elu_f((lo + hi) * inv0 + bb);
            UNPK2(lo, hi, a10); sW[(r0 + 1) * LDS_ + ca] = elu_f((lo + hi) * inv1 + ba);
            UNPK2(lo, hi, a11); sW[(r0 + 1) * LDS_ + cb] = elu_f((lo + hi) * inv1 + bb);
        }
        __syncthreads();
    }

    // ---- layer 2 linear: h2[n][0:2], f split 8 ways + shfl reduce ----
    {
        const int n = tid >> 3, fs = tid & 7;
        const float* xr = sW + n * LDS_ + fs * 16;
        const ull* w2o0 = (const ull*)&sW2T[0 * 128 + fs * 16];
        const ull* w2o1 = (const ull*)&sW2T[1 * 128 + fs * 16];
        ull acc0 = 0ULL, acc1 = 0ULL;
#pragma unroll
        for (int fp = 0; fp < 8; fp++) {
            const ull xp = *(const ull*)&xr[fp * 2];
            FFMA2(acc0, xp, w2o0[fp], acc0);
            FFMA2(acc1, xp, w2o1[fp], acc1);
        }
        float l0, h0, l1, h1;
        UNPK2(l0, h0, acc0); UNPK2(l1, h1, acc1);
        float p0 = l0 + h0, p1 = l1 + h1;
#pragma unroll
        for (int d = 4; d > 0; d >>= 1) {
            p0 += __shfl_xor_sync(0xffffffffu, p0, d);
            p1 += __shfl_xor_sync(0xffffffffu, p1, d);
        }
        if (fs == 0) { sH2[2 * n] = p0; sH2[2 * n + 1] = p1; }
    }
    __syncthreads();
    if (tid < 128) {
        int n = tid;
        float t0 = tanh_fast(sH2[2 * n]);
        float t1 = tanh_fast(sH2[2 * n + 1]);
        sDST2[n] = t0 * sMISC[2] + t1 * sMISC[3];
        if (n == 127) sMISC[6] = t0 * sMISC[0] + t1 * sMISC[1];
    }
    __syncthreads();

    // ---- ego-node attention row (i = 127), softmax, AV, log_softmax ----
    if (tid < 32) {
        float src = sMISC[6];
        float l[4];
#pragma unroll
        for (int g = 0; g < 4; g++) {
            int j = g * 32 + lane;
            float v = src + sDST2[j];
            v = fmaxf(v, 0.2f * v);
            unsigned bits = sADJ[127 * 4 + g];
            l[g] = ((bits >> lane) & 1u) ? v : -1e9f;
        }
        float m = fmaxf(fmaxf(l[0], l[1]), fmaxf(l[2], l[3]));
#pragma unroll
        for (int d = 16; d > 0; d >>= 1) m = fmaxf(m, __shfl_xor_sync(0xffffffffu, m, d));
        float sum = 0.0f, a0 = 0.0f, a1 = 0.0f;
#pragma unroll
        for (int g = 0; g < 4; g++) {
            int j = g * 32 + lane;
            float e = __expf(l[g] - m);
            sum += e;
            a0 += e * sH2[2 * j];
            a1 += e * sH2[2 * j + 1];
        }
#pragma unroll
        for (int d = 16; d > 0; d >>= 1) {
            sum += __shfl_xor_sync(0xffffffffu, sum, d);
            a0  += __shfl_xor_sync(0xffffffffu, a0, d);
            a1  += __shfl_xor_sync(0xffffffffu, a1, d);
        }
        if (lane == 0) {
            float inv = 1.0f / sum;
            float o0 = a0 * inv + sMISC[4];
            float o1 = a1 * inv + sMISC[5];
            float mm  = fmaxf(o0, o1);
            float lse = mm + logf(expf(o0 - mm) + expf(o1 - mm));
            g_partial[(s * BATCH + b) * 2 + 0] = o0 - lse;
            g_partial[(s * BATCH + b) * 2 + 1] = o1 - lse;
        }
    }

    // ---- last-CTA final reduce (mean over S) ----
    if (tid == 0) {
        __threadfence();
        int old = atomicAdd(&g_count, 1);
        sLast = (old == (S_MC * BATCH - 1)) ? 1 : 0;
    }
    __syncthreads();
    if (sLast) {
        if (tid < 256) {
            const volatile float* gp = g_partial;
            float v = gp[tid] + gp[256 + tid] + gp[512 + tid] + gp[768 + tid];
            out[tid] = 0.25f * v;
        }
        if (tid == 0) g_count = 0;
    }
}

extern "C" void kernel_launch(void* const* d_in, const int* in_sizes, int n_in,
                              void* d_out, int out_size)
{
    const float* x      = (const float*)d_in[0];
    const float* emb    = (const float*)d_in[1];
    const int*   adj    = (const int*)d_in[2];
    const float* w1     = (const float*)d_in[3];
    const float* a_src1 = (const float*)d_in[4];
    const float* a_dst1 = (const float*)d_in[5];
    const float* b1     = (const float*)d_in[6];
    const float* w2     = (const float*)d_in[7];
    const float* a_src2 = (const float*)d_in[8];
    const float* a_dst2 = (const float*)d_in[9];
    const float* b2     = (const float*)d_in[10];

    cudaFuncSetAttribute(gat_fused_kernel,
                         cudaFuncAttributeMaxDynamicSharedMemorySize, SMEM_BYTES);

    gat_fused_kernel<<<S_MC * BATCH, NTH, SMEM_BYTES>>>(
        x, emb, adj, w1, a_src1, a_dst1, b1, w2, a_src2, a_dst2, b2,
        (float*)d_out);
}

// round 7
// speedup vs baseline: 2.4457x; 1.7374x over previous
#include <cuda_runtime.h>
#include <cuda_bf16.h>
#include <math.h>

// Problem constants
#define S_MC   4
#define BATCH  128
#define NN     128
#define F0     64
#define EMBD   64
#define H1     8
#define F1     16
#define F2     2

#define NTH    1024
#define LDS_   132     // 132 ≡ 4 (mod 32) banks: consecutive rows -> consecutive bank quads

// SMEM layout (floats)
#define OFF_X     0          // 16896: x0 during GEMM1; then EPACK[1024]x4 + SRCP[1024]x4
#define OFF_W     16896      // 16896: W1^T [c][f] -> xs2 [n][c]
#define OFF_H     33792      // 16896: h^T [c][n]
#define OFF_ADJ   50688      // 512 uint32
#define OFF_P1S   51200      // 128
#define OFF_P1D   51328      // 128
#define OFF_B1    51456      // 16
#define OFF_W2T   51472      // 256
#define OFF_H2    51728      // 256
#define OFF_DST2  51984      // 128
#define OFF_MISC  52112      // 16
#define SMEM_FLOATS 52128
#define SMEM_BYTES (SMEM_FLOATS * 4)   // 208512

typedef unsigned long long ull;

#define FFMA2(d, a, b, c) \
    asm("fma.rn.f32x2 %0, %1, %2, %3;" : "=l"(d) : "l"(a), "l"(b), "l"(c))
#define UNPK2(lo, hi, p) \
    asm("mov.b64 {%0, %1}, %2;" : "=f"(lo), "=f"(hi) : "l"(p))
#define CVT_TF32(u, f) \
    asm("cvt.rna.tf32.f32 %0, %1;" : "=r"(u) : "f"(f))
#define MMA_TF32(c0, c1, c2, c3, a0, a1, a2, a3, b0, b1) \
    asm("mma.sync.aligned.m16n8k8.row.col.f32.tf32.tf32.f32 " \
        "{%0,%1,%2,%3}, {%4,%5,%6,%7}, {%8,%9}, {%0,%1,%2,%3};" \
        : "+f"(c0), "+f"(c1), "+f"(c2), "+f"(c3) \
        : "r"(a0), "r"(a1), "r"(a2), "r"(a3), "r"(b0), "r"(b1))

__device__ float g_partial[S_MC * BATCH * F2];
__device__ int   g_count;

__device__ __forceinline__ float tanh_fast(float x) {
    float y;
    asm("tanh.approx.f32 %0, %1;" : "=f"(y) : "f"(x));
    return y;
}
__device__ __forceinline__ float elu_f(float x) {
    return x > 0.0f ? x : (__expf(x) - 1.0f);
}

__global__ void __launch_bounds__(NTH, 1)
gat_fused_kernel(const float* __restrict__ x,
                 const float* __restrict__ emb,
                 const int*   __restrict__ adj,
                 const float* __restrict__ w1,
                 const float* __restrict__ a_src1,
                 const float* __restrict__ a_dst1,
                 const float* __restrict__ b1,
                 const float* __restrict__ w2,
                 const float* __restrict__ a_src2,
                 const float* __restrict__ a_dst2,
                 const float* __restrict__ b2,
                 float* __restrict__ out)
{
    extern __shared__ float sm[];
    float*    sX    = sm + OFF_X;     // x0 -> EPACK/SRCP
    float*    sW    = sm + OFF_W;     // W1^T -> xs2
    float*    sHT   = sm + OFF_H;     // h^T [c][n]
    unsigned* sADJ  = (unsigned*)(sm + OFF_ADJ);
    float*    sP1S  = sm + OFF_P1S;
    float*    sP1D  = sm + OFF_P1D;
    float*    sB1   = sm + OFF_B1;
    float*    sW2T  = sm + OFF_W2T;
    float*    sH2   = sm + OFF_H2;
    float*    sDST2 = sm + OFF_DST2;
    float*    sMISC = sm + OFF_MISC;
    __shared__ int sLast;

    const int tid = threadIdx.x;
    const int sb  = blockIdx.x;
    const int s   = sb >> 7;
    const int b   = sb & 127;
    const int warp = tid >> 5, lane = tid & 31;

    // ---- stage x0 = concat(x[b], emb[b]) : [128][128] ----
    {
        const float4* xv = (const float4*)(x   + (size_t)b * NN * F0);
        const float4* ev = (const float4*)(emb + (size_t)b * NN * EMBD);
        for (int i = tid; i < NN * 32; i += NTH) {
            int n = i >> 5, c4 = i & 31;
            float4 v = (c4 < 16) ? xv[n * 16 + c4] : ev[n * 16 + (c4 - 16)];
            *(float4*)&sX[n * LDS_ + c4 * 4] = v;
        }
    }
    // ---- stage W1[s] transposed: sW[c][f], c = head*16+o ----
    {
        const float4* wv = (const float4*)(w1 + (size_t)s * H1 * 128 * F1);
        for (int i = tid; i < 4096; i += NTH) {
            int head = i >> 9;
            int rem  = i & 511;
            int f = rem >> 2, o4 = rem & 3;
            float4 v = wv[i];
            int c = head * 16 + o4 * 4;
            sW[(c + 0) * LDS_ + f] = v.x;
            sW[(c + 1) * LDS_ + f] = v.y;
            sW[(c + 2) * LDS_ + f] = v.z;
            sW[(c + 3) * LDS_ + f] = v.w;
        }
    }
    // ---- small params ----
    if (tid < 128) { sP1S[tid] = a_src1[s * 128 + tid]; sP1D[tid] = a_dst1[s * 128 + tid]; }
    if (tid < 16)  sB1[tid] = b1[tid];
    if (tid < 256) { int f = tid >> 1, o = tid & 1; sW2T[o * 128 + f] = w2[s * 256 + tid]; }
    if (tid == 0) {
        sMISC[0] = a_src2[s * 2 + 0]; sMISC[1] = a_src2[s * 2 + 1];
        sMISC[2] = a_dst2[s * 2 + 0]; sMISC[3] = a_dst2[s * 2 + 1];
        sMISC[4] = b2[0];             sMISC[5] = b2[1];
    }
    // ---- adjacency bitmask: 128 rows * 4 words ----
    {
        const int* arow = adj + (size_t)b * NN * NN;
        for (int t = warp; t < 512; t += 32) {
            int i = t >> 2, g = t & 3;
            int v = arow[i * NN + g * 32 + lane];
            unsigned bits = __ballot_sync(0xffffffffu, v != 0);
            if (lane == 0) sADJ[t] = bits;
        }
    }
    __syncthreads();

    // ---- GEMM1: hT[c][n] = sum_f x0[n][f] * wT[c][f]  (fp32 FFMA2) ----
    {
        const int ct = tid & 63, rt = tid >> 6;
        const int c0 = ct, c1 = ct + 64;
        const int r0 = rt * 8;
        ull acc0[8], acc1[8];
#pragma unroll
        for (int r = 0; r < 8; r++) { acc0[r] = 0ULL; acc1[r] = 0ULL; }

        const float* w0 = sW + c0 * LDS_;
        const float* w1r = sW + c1 * LDS_;
        for (int f = 0; f < 128; f += 4) {
            const ulonglong2 b0 = *(const ulonglong2*)&w0[f];
            const ulonglong2 b1v = *(const ulonglong2*)&w1r[f];
#pragma unroll
            for (int r = 0; r < 8; r++) {
                const ulonglong2 ap = *(const ulonglong2*)&sX[(r0 + r) * LDS_ + f];
                FFMA2(acc0[r], ap.x, b0.x, acc0[r]);
                FFMA2(acc0[r], ap.y, b0.y, acc0[r]);
                FFMA2(acc1[r], ap.x, b1v.x, acc1[r]);
                FFMA2(acc1[r], ap.y, b1v.y, acc1[r]);
            }
        }
        float v0[8], v1[8];
#pragma unroll
        for (int r = 0; r < 8; r++) {
            float lo, hi;
            UNPK2(lo, hi, acc0[r]); v0[r] = lo + hi;
            UNPK2(lo, hi, acc1[r]); v1[r] = lo + hi;
        }
        *(float4*)&sHT[c0 * LDS_ + r0]     = make_float4(v0[0], v0[1], v0[2], v0[3]);
        *(float4*)&sHT[c0 * LDS_ + r0 + 4] = make_float4(v0[4], v0[5], v0[6], v0[7]);
        *(float4*)&sHT[c1 * LDS_ + r0]     = make_float4(v1[0], v1[1], v1[2], v1[3]);
        *(float4*)&sHT[c1 * LDS_ + r0 + 4] = make_float4(v1[4], v1[5], v1[6], v1[7]);
    }
    __syncthreads();

    // ---- att projections -> packed exp factors (into dead x0 buffer) ----
    // EPACK[idx] = {dst, exp(dst), exp(0.2 dst), -}; SRCP[idx] = {exp(src), exp(0.2 src), src, -}
    {
        const int head = tid >> 7, n = tid & 127;
        const float* hcol = sHT + (head * 16) * LDS_ + n;
        float sa = 0.0f, da = 0.0f;
#pragma unroll
        for (int o = 0; o < 16; o++) {
            float t = tanh_fast(hcol[o * LDS_]);
            sa += t * sP1S[head * 16 + o];
            da += t * sP1D[head * 16 + o];
        }
        float4* EP = (float4*)sX;
        float4* SP = EP + 1024;
        EP[tid] = make_float4(da, __expf(da), __expf(0.2f * da), 0.0f);
        SP[tid] = make_float4(__expf(sa), __expf(0.2f * sa), sa, 0.0f);
    }
    __syncthreads();

    // ---- flash-style AV: 64 jobs (head x 16-row tile), tf32 mma.sync ----
    {
        const int l3 = lane & 3, g = lane >> 2;
        const float4* EP = (const float4*)sX;
        const float4* SP = EP + 1024;
        for (int job = warp; job < 64; job += 32) {
            const int head = job >> 3, rt = job & 7;
            const int i0 = rt * 16;
            const int ra = i0 + g, rb = ra + 8;
            const float4 spa = SP[head * 128 + ra];   // {Ei, Ei2, src}
            const float4 spb = SP[head * 128 + rb];
            float c00 = 0.f, c01 = 0.f, c02 = 0.f, c03 = 0.f;
            float c10 = 0.f, c11 = 0.f, c12 = 0.f, c13 = 0.f;
            float suma = 0.f, sumb = 0.f;
            const float* hb0p = sHT + (head * 16 + g) * LDS_;
            const float* hb1p = sHT + (head * 16 + 8 + g) * LDS_;
            const float4* EPh = EP + head * 128;
#pragma unroll
            for (int w4 = 0; w4 < 4; w4++) {
                const unsigned wa = sADJ[ra * 4 + w4] >> l3;
                const unsigned wb = sADJ[rb * 4 + w4] >> l3;
#pragma unroll
                for (int kk = 0; kk < 4; kk++) {
                    const int j0 = (w4 * 4 + kk) * 8 + l3;
                    const float4 ep0 = EPh[j0];
                    const float4 ep1 = EPh[j0 + 4];
                    float ea0 = ((spa.z + ep0.x) > 0.f) ? spa.x * ep0.y : spa.y * ep0.z;
                    float ea1 = ((spa.z + ep1.x) > 0.f) ? spa.x * ep1.y : spa.y * ep1.z;
                    float eb0 = ((spb.z + ep0.x) > 0.f) ? spb.x * ep0.y : spb.y * ep0.z;
                    float eb1 = ((spb.z + ep1.x) > 0.f) ? spb.x * ep1.y : spb.y * ep1.z;
                    if (!((wa >> (kk * 8)) & 1u))     ea0 = 0.f;
                    if (!((wa >> (kk * 8 + 4)) & 1u)) ea1 = 0.f;
                    if (!((wb >> (kk * 8)) & 1u))     eb0 = 0.f;
                    if (!((wb >> (kk * 8 + 4)) & 1u)) eb1 = 0.f;
                    unsigned a0, a1, a2, a3;
                    CVT_TF32(a0, ea0); CVT_TF32(a1, eb0);
                    CVT_TF32(a2, ea1); CVT_TF32(a3, eb1);
                    suma += __uint_as_float(a0) + __uint_as_float(a2);
                    sumb += __uint_as_float(a1) + __uint_as_float(a3);
                    unsigned b0, b1, b2, b3;
                    CVT_TF32(b0, hb0p[j0]); CVT_TF32(b1, hb0p[j0 + 4]);
                    CVT_TF32(b2, hb1p[j0]); CVT_TF32(b3, hb1p[j0 + 4]);
                    MMA_TF32(c00, c01, c02, c03, a0, a1, a2, a3, b0, b1);
                    MMA_TF32(c10, c11, c12, c13, a0, a1, a2, a3, b2, b3);
                }
            }
            suma += __shfl_xor_sync(0xffffffffu, suma, 1);
            suma += __shfl_xor_sync(0xffffffffu, suma, 2);
            sumb += __shfl_xor_sync(0xffffffffu, sumb, 1);
            sumb += __shfl_xor_sync(0xffffffffu, sumb, 2);
            const float inva = 1.0f / suma, invb = 1.0f / sumb;
            const int cl0 = l3 * 2;
            const float bi00 = sB1[cl0], bi01 = sB1[cl0 + 1];
            const float bi10 = sB1[cl0 + 8], bi11 = sB1[cl0 + 9];
            const int c0 = head * 16;
            *(float2*)&sW[ra * LDS_ + c0 + cl0] =
                make_float2(elu_f(c00 * inva + bi00), elu_f(c01 * inva + bi01));
            *(float2*)&sW[ra * LDS_ + c0 + 8 + cl0] =
                make_float2(elu_f(c10 * inva + bi10), elu_f(c11 * inva + bi11));
            *(float2*)&sW[rb * LDS_ + c0 + cl0] =
                make_float2(elu_f(c02 * invb + bi00), elu_f(c03 * invb + bi01));
            *(float2*)&sW[rb * LDS_ + c0 + 8 + cl0] =
                make_float2(elu_f(c12 * invb + bi10), elu_f(c13 * invb + bi11));
        }
    }
    __syncthreads();

    // ---- layer 2 linear: h2[n][0:2], f split 8 ways + shfl reduce ----
    {
        const int n = tid >> 3, fs = tid & 7;
        const float* xr = sW + n * LDS_ + fs * 16;
        const ull* w2o0 = (const ull*)&sW2T[0 * 128 + fs * 16];
        const ull* w2o1 = (const ull*)&sW2T[1 * 128 + fs * 16];
        ull acc0 = 0ULL, acc1 = 0ULL;
#pragma unroll
        for (int fp = 0; fp < 8; fp++) {
            const ull xp = *(const ull*)&xr[fp * 2];
            FFMA2(acc0, xp, w2o0[fp], acc0);
            FFMA2(acc1, xp, w2o1[fp], acc1);
        }
        float l0, h0, l1, h1;
        UNPK2(l0, h0, acc0); UNPK2(l1, h1, acc1);
        float p0 = l0 + h0, p1 = l1 + h1;
#pragma unroll
        for (int d = 4; d > 0; d >>= 1) {
            p0 += __shfl_xor_sync(0xffffffffu, p0, d);
            p1 += __shfl_xor_sync(0xffffffffu, p1, d);
        }
        if (fs == 0) { sH2[2 * n] = p0; sH2[2 * n + 1] = p1; }
    }
    __syncthreads();
    if (tid < 128) {
        int n = tid;
        float t0 = tanh_fast(sH2[2 * n]);
        float t1 = tanh_fast(sH2[2 * n + 1]);
        sDST2[n] = t0 * sMISC[2] + t1 * sMISC[3];
        if (n == 127) sMISC[6] = t0 * sMISC[0] + t1 * sMISC[1];
    }
    __syncthreads();

    // ---- ego-node attention row (i = 127), softmax, AV, log_softmax ----
    if (tid < 32) {
        float src = sMISC[6];
        float l[4];
#pragma unroll
        for (int gg = 0; gg < 4; gg++) {
            int j = gg * 32 + lane;
            float v = src + sDST2[j];
            v = fmaxf(v, 0.2f * v);
            unsigned bits = sADJ[127 * 4 + gg];
            l[gg] = ((bits >> lane) & 1u) ? v : -1e9f;
        }
        float m = fmaxf(fmaxf(l[0], l[1]), fmaxf(l[2], l[3]));
#pragma unroll
        for (int d = 16; d > 0; d >>= 1) m = fmaxf(m, __shfl_xor_sync(0xffffffffu, m, d));
        float sum = 0.0f, a0 = 0.0f, a1 = 0.0f;
#pragma unroll
        for (int gg = 0; gg < 4; gg++) {
            int j = gg * 32 + lane;
            float e = __expf(l[gg] - m);
            sum += e;
            a0 += e * sH2[2 * j];
            a1 += e * sH2[2 * j + 1];
        }
#pragma unroll
        for (int d = 16; d > 0; d >>= 1) {
            sum += __shfl_xor_sync(0xffffffffu, sum, d);
            a0  += __shfl_xor_sync(0xffffffffu, a0, d);
            a1  += __shfl_xor_sync(0xffffffffu, a1, d);
        }
        if (lane == 0) {
            float inv = 1.0f / sum;
            float o0 = a0 * inv + sMISC[4];
            float o1 = a1 * inv + sMISC[5];
            float mm  = fmaxf(o0, o1);
            float lse = mm + logf(expf(o0 - mm) + expf(o1 - mm));
            g_partial[(s * BATCH + b) * 2 + 0] = o0 - lse;
            g_partial[(s * BATCH + b) * 2 + 1] = o1 - lse;
        }
    }

    // ---- last-CTA final reduce (mean over S) ----
    if (tid == 0) {
        __threadfence();
        int old = atomicAdd(&g_count, 1);
        sLast = (old == (S_MC * BATCH - 1)) ? 1 : 0;
    }
    __syncthreads();
    if (sLast) {
        if (tid < 256) {
            const volatile float* gp = g_partial;
            float v = gp[tid] + gp[256 + tid] + gp[512 + tid] + gp[768 + tid];
            out[tid] = 0.25f * v;
        }
        if (tid == 0) g_count = 0;
    }
}

extern "C" void kernel_launch(void* const* d_in, const int* in_sizes, int n_in,
                              void* d_out, int out_size)
{
    const float* x      = (const float*)d_in[0];
    const float* emb    = (const float*)d_in[1];
    const int*   adj    = (const int*)d_in[2];
    const float* w1     = (const float*)d_in[3];
    const float* a_src1 = (const float*)d_in[4];
    const float* a_dst1 = (const float*)d_in[5];
    const float* b1     = (const float*)d_in[6];
    const float* w2     = (const float*)d_in[7];
    const float* a_src2 = (const float*)d_in[8];
    const float* a_dst2 = (const float*)d_in[9];
    const float* b2     = (const float*)d_in[10];

    cudaFuncSetAttribute(gat_fused_kernel,
                         cudaFuncAttributeMaxDynamicSharedMemorySize, SMEM_BYTES);

    gat_fused_kernel<<<S_MC * BATCH, NTH, SMEM_BYTES>>>(
        x, emb, adj, w1, a_src1, a_dst1, b1, w2, a_src2, a_dst2, b2,
        (float*)d_out);
}

// round 10
// speedup vs baseline: 3.1361x; 1.2823x over previous
#include <cuda_runtime.h>
#include <cuda_bf16.h>
#include <math.h>

// Problem constants
#define S_MC   4
#define BATCH  128
#define NN     128
#define F0     64
#define EMBD   64
#define H1     8
#define F1     16
#define F2     2

#define NTH    1024
#define SD     144   // stride for sX/sW: (144/4)%8=4 -> conflict-free m16n8k8 lds.128
#define HD     132   // stride for sHT: conflict-free lds.32 column reads

// SMEM layout (floats)
#define OFF_X     0          // 18432: x0 (tf32) during GEMM1; then EP/SP packs
#define OFF_W     18432      // 18432: W1^T (tf32) [c][f] -> xs2 [n][c]
#define OFF_H     36864      // 16896: h^T [c][n] (tf32-rounded)
#define OFF_ADJ   53760      // 512 uint32
#define OFF_P1S   54272      // 128
#define OFF_P1D   54400      // 128
#define OFF_B1    54528      // 16
#define OFF_W2T   54544      // 256
#define OFF_H2    54800      // 256
#define OFF_DST2  55056      // 128
#define OFF_MISC  55184      // 16
#define SMEM_FLOATS 55200
#define SMEM_BYTES (SMEM_FLOATS * 4)   // 220800

typedef unsigned long long ull;

#define FFMA2(d, a, b, c) \
    asm("fma.rn.f32x2 %0, %1, %2, %3;" : "=l"(d) : "l"(a), "l"(b), "l"(c))
#define UNPK2(lo, hi, p) \
    asm("mov.b64 {%0, %1}, %2;" : "=f"(lo), "=f"(hi) : "l"(p))
#define CVT_TF32(u, f) \
    asm("cvt.rna.tf32.f32 %0, %1;" : "=r"(u) : "f"(f))
#define MMA_TF32(c0, c1, c2, c3, a0, a1, a2, a3, b0, b1) \
    asm("mma.sync.aligned.m16n8k8.row.col.f32.tf32.tf32.f32 " \
        "{%0,%1,%2,%3}, {%4,%5,%6,%7}, {%8,%9}, {%0,%1,%2,%3};" \
        : "+f"(c0), "+f"(c1), "+f"(c2), "+f"(c3) \
        : "r"(a0), "r"(a1), "r"(a2), "r"(a3), "r"(b0), "r"(b1))

__device__ float g_partial[S_MC * BATCH * F2];
__device__ int   g_count;

__device__ __forceinline__ float tanh_fast(float x) {
    float y;
    asm("tanh.approx.f32 %0, %1;" : "=f"(y) : "f"(x));
    return y;
}
__device__ __forceinline__ float elu_f(float x) {
    return x > 0.0f ? x : (__expf(x) - 1.0f);
}
__device__ __forceinline__ float tf32r(float x) {  // round to tf32, return as float
    unsigned u; CVT_TF32(u, x); return __uint_as_float(u);
}

__global__ void __launch_bounds__(NTH, 1)
gat_fused_kernel(const float* __restrict__ x,
                 const float* __restrict__ emb,
                 const int*   __restrict__ adj,
                 const float* __restrict__ w1,
                 const float* __restrict__ a_src1,
                 const float* __restrict__ a_dst1,
                 const float* __restrict__ b1,
                 const float* __restrict__ w2,
                 const float* __restrict__ a_src2,
                 const float* __restrict__ a_dst2,
                 const float* __restrict__ b2,
                 float* __restrict__ out)
{
    extern __shared__ float sm[];
    float*    sX    = sm + OFF_X;     // x0(tf32) -> EP/SP
    float*    sW    = sm + OFF_W;     // W1^T(tf32) -> xs2
    float*    sHT   = sm + OFF_H;     // h^T [c][n], tf32-rounded
    unsigned* sADJ  = (unsigned*)(sm + OFF_ADJ);
    float*    sP1S  = sm + OFF_P1S;
    float*    sP1D  = sm + OFF_P1D;
    float*    sB1   = sm + OFF_B1;
    float*    sW2T  = sm + OFF_W2T;
    float*    sH2   = sm + OFF_H2;
    float*    sDST2 = sm + OFF_DST2;
    float*    sMISC = sm + OFF_MISC;
    __shared__ int sLast;

    const int tid = threadIdx.x;
    const int sb  = blockIdx.x;
    const int s   = sb >> 7;
    const int b   = sb & 127;
    const int warp = tid >> 5, lane = tid & 31;
    const int g = lane >> 2, l3 = lane & 3;

    // ---- stage x0 = concat(x[b], emb[b]), rounded to tf32 ----
    {
        const float4* xv = (const float4*)(x   + (size_t)b * NN * F0);
        const float4* ev = (const float4*)(emb + (size_t)b * NN * EMBD);
        for (int i = tid; i < NN * 32; i += NTH) {
            int n = i >> 5, c4 = i & 31;
            float4 v = (c4 < 16) ? xv[n * 16 + c4] : ev[n * 16 + (c4 - 16)];
            v.x = tf32r(v.x); v.y = tf32r(v.y); v.z = tf32r(v.z); v.w = tf32r(v.w);
            *(float4*)&sX[n * SD + c4 * 4] = v;
        }
    }
    // ---- stage W1[s] transposed (tf32): sW[c][f], c = head*16+o ----
    {
        const float4* wv = (const float4*)(w1 + (size_t)s * H1 * 128 * F1);
        for (int i = tid; i < 4096; i += NTH) {
            int head = i >> 9;
            int rem  = i & 511;
            int f = rem >> 2, o4 = rem & 3;
            float4 v = wv[i];
            int c = head * 16 + o4 * 4;
            sW[(c + 0) * SD + f] = tf32r(v.x);
            sW[(c + 1) * SD + f] = tf32r(v.y);
            sW[(c + 2) * SD + f] = tf32r(v.z);
            sW[(c + 3) * SD + f] = tf32r(v.w);
        }
    }
    // ---- small params ----
    if (tid < 128) { sP1S[tid] = a_src1[s * 128 + tid]; sP1D[tid] = a_dst1[s * 128 + tid]; }
    if (tid < 16)  sB1[tid] = b1[tid];
    if (tid < 256) { int f = tid >> 1, o = tid & 1; sW2T[o * 128 + f] = w2[s * 256 + tid]; }
    if (tid == 0) {
        sMISC[0] = a_src2[s * 2 + 0]; sMISC[1] = a_src2[s * 2 + 1];
        sMISC[2] = a_dst2[s * 2 + 0]; sMISC[3] = a_dst2[s * 2 + 1];
        sMISC[4] = b2[0];             sMISC[5] = b2[1];
    }
    // ---- adjacency bitmask: 128 rows * 4 words ----
    {
        const int* arow = adj + (size_t)b * NN * NN;
        for (int t = warp; t < 512; t += 32) {
            int i = t >> 2, gg = t & 3;
            int v = arow[i * NN + gg * 32 + lane];
            unsigned bits = __ballot_sync(0xffffffffu, v != 0);
            if (lane == 0) sADJ[t] = bits;
        }
    }
    __syncthreads();

    // ---- GEMM1 (tf32 tensor): hT[c][n] = sum_f wT[c][f] * x0[n][f] ----
    // m16n8k8 with permuted-k fragments: thread feeds physical cols {4l3..4l3+3}
    // for two consecutive mma steps (consistent on A and B -> exact same sum).
    {
        const int ct = (warp >> 2) * 16;       // 8 c-tiles, 4 warps each
        const int ra = ct + g, rb = ra + 8;
        const float* wra = sW + ra * SD;
        const float* wrb = sW + rb * SD;
#pragma unroll
        for (int q = 0; q < 4; q++) {
            const int n0 = ((warp & 3) + 4 * q) * 8;
            const float* xb = sX + (n0 + g) * SD;
            float c0 = 0.f, c1 = 0.f, c2 = 0.f, c3 = 0.f;
#pragma unroll
            for (int t = 0; t < 8; t++) {
                const int o = 16 * t + 4 * l3;
                const float4 A0 = *(const float4*)&wra[o];
                const float4 A1 = *(const float4*)&wrb[o];
                const float4 Bv = *(const float4*)&xb[o];
                MMA_TF32(c0, c1, c2, c3,
                         __float_as_uint(A0.x), __float_as_uint(A1.x),
                         __float_as_uint(A0.y), __float_as_uint(A1.y),
                         __float_as_uint(Bv.x), __float_as_uint(Bv.y));
                MMA_TF32(c0, c1, c2, c3,
                         __float_as_uint(A0.z), __float_as_uint(A1.z),
                         __float_as_uint(A0.w), __float_as_uint(A1.w),
                         __float_as_uint(Bv.z), __float_as_uint(Bv.w));
            }
            // D: c0,c1 -> row ra cols n0+2l3,+1 ; c2,c3 -> row rb. Round to tf32
            // so the AV B-operand can use raw bits with exact normalization.
            *(float2*)&sHT[ra * HD + n0 + 2 * l3] = make_float2(tf32r(c0), tf32r(c1));
            *(float2*)&sHT[rb * HD + n0 + 2 * l3] = make_float2(tf32r(c2), tf32r(c3));
        }
    }
    __syncthreads();

    // ---- att projections -> packed exp factors (into dead x0 buffer) ----
    // EP[idx] = {exp(dst), exp(0.2 dst)}; SP[idx] = {exp(src), exp(0.2 src)}
    {
        const int head = tid >> 7, n = tid & 127;
        const float* hcol = sHT + (head * 16) * HD + n;
        float sa = 0.0f, da = 0.0f;
#pragma unroll
        for (int o = 0; o < 16; o++) {
            float t = tanh_fast(hcol[o * HD]);
            sa += t * sP1S[head * 16 + o];
            da += t * sP1D[head * 16 + o];
        }
        float2* EP = (float2*)sX;
        float2* SP = EP + 1024;
        EP[tid] = make_float2(__expf(da), __expf(0.2f * da));
        SP[tid] = make_float2(__expf(sa), __expf(0.2f * sa));
    }
    __syncthreads();

    // ---- flash-style AV: 64 jobs (head x 16-row tile), tf32 mma.sync ----
    // e^lrelu(src+dst) == max(e^src * e^dst, e^{0.2 src} * e^{0.2 dst})
    {
        const float2* EP = (const float2*)sX;
        const float2* SP = EP + 1024;
        for (int job = warp; job < 64; job += 32) {
            const int head = job >> 3, rt = job & 7;
            const int i0 = rt * 16;
            const int ra = i0 + g, rb = ra + 8;
            const float2 spa = SP[head * 128 + ra];   // {Es, Es2}
            const float2 spb = SP[head * 128 + rb];
            float c00 = 0.f, c01 = 0.f, c02 = 0.f, c03 = 0.f;
            float c10 = 0.f, c11 = 0.f, c12 = 0.f, c13 = 0.f;
            float suma = 0.f, sumb = 0.f;
            const float* hb0p = sHT + (head * 16 + g) * HD;
            const float* hb1p = sHT + (head * 16 + 8 + g) * HD;
            const float2* EPh = EP + head * 128;
#pragma unroll
            for (int w4 = 0; w4 < 4; w4++) {
                const unsigned wa = sADJ[ra * 4 + w4] >> l3;
                const unsigned wb = sADJ[rb * 4 + w4] >> l3;
#pragma unroll
                for (int kk = 0; kk < 4; kk++) {
                    const int j0 = (w4 * 4 + kk) * 8 + l3;
                    const float2 ep0 = EPh[j0];
                    const float2 ep1 = EPh[j0 + 4];
                    float ea0 = fmaxf(spa.x * ep0.x, spa.y * ep0.y);
                    float ea1 = fmaxf(spa.x * ep1.x, spa.y * ep1.y);
                    float eb0 = fmaxf(spb.x * ep0.x, spb.y * ep0.y);
                    float eb1 = fmaxf(spb.x * ep1.x, spb.y * ep1.y);
                    if (!((wa >> (kk * 8)) & 1u))     ea0 = 0.f;
                    if (!((wa >> (kk * 8 + 4)) & 1u)) ea1 = 0.f;
                    if (!((wb >> (kk * 8)) & 1u))     eb0 = 0.f;
                    if (!((wb >> (kk * 8 + 4)) & 1u)) eb1 = 0.f;
                    unsigned a0, a1, a2, a3;
                    CVT_TF32(a0, ea0); CVT_TF32(a1, eb0);
                    CVT_TF32(a2, ea1); CVT_TF32(a3, eb1);
                    suma += __uint_as_float(a0) + __uint_as_float(a2);
                    sumb += __uint_as_float(a1) + __uint_as_float(a3);
                    MMA_TF32(c00, c01, c02, c03, a0, a1, a2, a3,
                             __float_as_uint(hb0p[j0]), __float_as_uint(hb0p[j0 + 4]));
                    MMA_TF32(c10, c11, c12, c13, a0, a1, a2, a3,
                             __float_as_uint(hb1p[j0]), __float_as_uint(hb1p[j0 + 4]));
                }
            }
            suma += __shfl_xor_sync(0xffffffffu, suma, 1);
            suma += __shfl_xor_sync(0xffffffffu, suma, 2);
            sumb += __shfl_xor_sync(0xffffffffu, sumb, 1);
            sumb += __shfl_xor_sync(0xffffffffu, sumb, 2);
            const float inva = 1.0f / suma, invb = 1.0f / sumb;
            const int cl0 = l3 * 2;
            const float bi00 = sB1[cl0], bi01 = sB1[cl0 + 1];
            const float bi10 = sB1[cl0 + 8], bi11 = sB1[cl0 + 9];
            const int c0c = head * 16;
            *(float2*)&sW[ra * SD + c0c + cl0] =
                make_float2(elu_f(c00 * inva + bi00), elu_f(c01 * inva + bi01));
            *(float2*)&sW[ra * SD + c0c + 8 + cl0] =
                make_float2(elu_f(c10 * inva + bi10), elu_f(c11 * inva + bi11));
            *(float2*)&sW[rb * SD + c0c + cl0] =
                make_float2(elu_f(c02 * invb + bi00), elu_f(c03 * invb + bi01));
            *(float2*)&sW[rb * SD + c0c + 8 + cl0] =
                make_float2(elu_f(c12 * invb + bi10), elu_f(c13 * invb + bi11));
        }
    }
    __syncthreads();

    // ---- layer 2 linear: h2[n][0:2], f split 8 ways + shfl reduce ----
    {
        const int n = tid >> 3, fs = tid & 7;
        const float* xr = sW + n * SD + fs * 16;
        const ull* w2o0 = (const ull*)&sW2T[0 * 128 + fs * 16];
        const ull* w2o1 = (const ull*)&sW2T[1 * 128 + fs * 16];
        ull acc0 = 0ULL, acc1 = 0ULL;
#pragma unroll
        for (int fp = 0; fp < 8; fp++) {
            const ull xp = *(const ull*)&xr[fp * 2];
            FFMA2(acc0, xp, w2o0[fp], acc0);
            FFMA2(acc1, xp, w2o1[fp], acc1);
        }
        float l0, h0, l1, h1;
        UNPK2(l0, h0, acc0); UNPK2(l1, h1, acc1);
        float p0 = l0 + h0, p1 = l1 + h1;
#pragma unroll
        for (int d = 4; d > 0; d >>= 1) {
            p0 += __shfl_xor_sync(0xffffffffu, p0, d);
            p1 += __shfl_xor_sync(0xffffffffu, p1, d);
        }
        if (fs == 0) { sH2[2 * n] = p0; sH2[2 * n + 1] = p1; }
    }
    __syncthreads();
    if (tid < 128) {
        int n = tid;
        float t0 = tanh_fast(sH2[2 * n]);
        float t1 = tanh_fast(sH2[2 * n + 1]);
        sDST2[n] = t0 * sMISC[2] + t1 * sMISC[3];
        if (n == 127) sMISC[6] = t0 * sMISC[0] + t1 * sMISC[1];
    }
    __syncthreads();

    // ---- ego-node attention row (i = 127), softmax, AV, log_softmax ----
    if (tid < 32) {
        float src = sMISC[6];
        float l[4];
#pragma unroll
        for (int gg = 0; gg < 4; gg++) {
            int j = gg * 32 + lane;
            float v = src + sDST2[j];
            v = fmaxf(v, 0.2f * v);
            unsigned bits = sADJ[127 * 4 + gg];
            l[gg] = ((bits >> lane) & 1u) ? v : -1e9f;
        }
        float m = fmaxf(fmaxf(l[0], l[1]), fmaxf(l[2], l[3]));
#pragma unroll
        for (int d = 16; d > 0; d >>= 1) m = fmaxf(m, __shfl_xor_sync(0xffffffffu, m, d));
        float sum = 0.0f, a0 = 0.0f, a1 = 0.0f;
#pragma unroll
        for (int gg = 0; gg < 4; gg++) {
            int j = gg * 32 + lane;
            float e = __expf(l[gg] - m);
            sum += e;
            a0 += e * sH2[2 * j];
            a1 += e * sH2[2 * j + 1];
        }
#pragma unroll
        for (int d = 16; d > 0; d >>= 1) {
            sum += __shfl_xor_sync(0xffffffffu, sum, d);
            a0  += __shfl_xor_sync(0xffffffffu, a0, d);
            a1  += __shfl_xor_sync(0xffffffffu, a1, d);
        }
        if (lane == 0) {
            float inv = 1.0f / sum;
            float o0 = a0 * inv + sMISC[4];
            float o1 = a1 * inv + sMISC[5];
            float mm  = fmaxf(o0, o1);
            float lse = mm + logf(expf(o0 - mm) + expf(o1 - mm));
            g_partial[(s * BATCH + b) * 2 + 0] = o0 - lse;
            g_partial[(s * BATCH + b) * 2 + 1] = o1 - lse;
        }
    }

    // ---- last-CTA final reduce (mean over S) ----
    if (tid == 0) {
        __threadfence();
        int old = atomicAdd(&g_count, 1);
        sLast = (old == (S_MC * BATCH - 1)) ? 1 : 0;
    }
    __syncthreads();
    if (sLast) {
        if (tid < 256) {
            const volatile float* gp = g_partial;
            float v = gp[tid] + gp[256 + tid] + gp[512 + tid] + gp[768 + tid];
            out[tid] = 0.25f * v;
        }
        if (tid == 0) g_count = 0;
    }
}

extern "C" void kernel_launch(void* const* d_in, const int* in_sizes, int n_in,
                              void* d_out, int out_size)
{
    const float* x      = (const float*)d_in[0];
    const float* emb    = (const float*)d_in[1];
    const int*   adj    = (const int*)d_in[2];
    const float* w1     = (const float*)d_in[3];
    const float* a_src1 = (const float*)d_in[4];
    const float* a_dst1 = (const float*)d_in[5];
    const float* b1     = (const float*)d_in[6];
    const float* w2     = (const float*)d_in[7];
    const float* a_src2 = (const float*)d_in[8];
    const float* a_dst2 = (const float*)d_in[9];
    const float* b2     = (const float*)d_in[10];

    cudaFuncSetAttribute(gat_fused_kernel,
                         cudaFuncAttributeMaxDynamicSharedMemorySize, SMEM_BYTES);

    gat_fused_kernel<<<S_MC * BATCH, NTH, SMEM_BYTES>>>(
        x, emb, adj, w1, a_src1, a_dst1, b1, w2, a_src2, a_dst2, b2,
        (float*)d_out);
}

// round 11
// speedup vs baseline: 3.9410x; 1.2566x over previous
#include <cuda_runtime.h>
#include <cuda_bf16.h>
#include <math.h>

// Problem constants
#define S_MC   4
#define BATCH  128
#define NN     128
#define F0     64
#define EMBD   64
#define H1     8
#define F1     16
#define F2     2

#define NTH    1024
#define SD     144   // stride for sX/sW fp32 tiles: conflict-free m16n8k8-style lds.128
#define HBD    68    // stride (32-bit words) for hB / emaskb: addr%32 = 4g+l3 -> conflict-free

// SMEM layout (32-bit word offsets)
#define OFF_X     0          // 18432: x0 fp32 during GEMM1; then EPB/EP2B/SP
#define OFF_W     18432      // 18432: W1^T fp32 -> xs2 fp32
#define OFF_HB    36864      // 8704: h as bf16x2 [c][j-pair], stride 68
#define OFF_MB    45568      // 8704: adj mask as bf16x2 {1.0/0.0} [i][j-pair], stride 68
#define OFF_P1S   54272      // 128
#define OFF_P1D   54400      // 128
#define OFF_B1    54528      // 16
#define OFF_W2T   54544      // 256
#define OFF_H2    54800      // 256
#define OFF_DST2  55056      // 128
#define OFF_MISC  55184      // 16
#define SMEM_FLOATS 55200
#define SMEM_BYTES (SMEM_FLOATS * 4)   // 220800

// sub-offsets inside OFF_X after GEMM1 (x0 dead)
#define OFF_EPB   0          // 512 words: bf16x2 {exp(dst_2p), exp(dst_2p+1)} per head
#define OFF_EP2B  512        // 512 words: 0.2-versions
#define OFF_SP    1024       // 2048 floats: float2 {exp(src), exp(0.2 src)} per (head,n)

typedef unsigned long long ull;

#define FFMA2(d, a, b, c) \
    asm("fma.rn.f32x2 %0, %1, %2, %3;" : "=l"(d) : "l"(a), "l"(b), "l"(c))
#define UNPK2(lo, hi, p) \
    asm("mov.b64 {%0, %1}, %2;" : "=f"(lo), "=f"(hi) : "l"(p))
#define CVT_TF32(u, f) \
    asm("cvt.rna.tf32.f32 %0, %1;" : "=r"(u) : "f"(f))
#define PACKBF(d, hi, lo) \
    asm("cvt.rn.bf16x2.f32 %0, %1, %2;" : "=r"(d) : "f"(hi), "f"(lo))
#define HMUL2B(d, a, b) \
    asm("mul.bf16x2 %0, %1, %2;" : "=r"(d) : "r"(a), "r"(b))
#define HMAX2B(d, a, b) \
    asm("max.bf16x2 %0, %1, %2;" : "=r"(d) : "r"(a), "r"(b))
#define MMA_TF32(c0, c1, c2, c3, a0, a1, a2, a3, b0, b1) \
    asm("mma.sync.aligned.m16n8k8.row.col.f32.tf32.tf32.f32 " \
        "{%0,%1,%2,%3}, {%4,%5,%6,%7}, {%8,%9}, {%0,%1,%2,%3};" \
        : "+f"(c0), "+f"(c1), "+f"(c2), "+f"(c3) \
        : "r"(a0), "r"(a1), "r"(a2), "r"(a3), "r"(b0), "r"(b1))
#define MMA_BF16(c0, c1, c2, c3, a0, a1, a2, a3, b0, b1) \
    asm("mma.sync.aligned.m16n8k16.row.col.f32.bf16.bf16.f32 " \
        "{%0,%1,%2,%3}, {%4,%5,%6,%7}, {%8,%9}, {%0,%1,%2,%3};" \
        : "+f"(c0), "+f"(c1), "+f"(c2), "+f"(c3) \
        : "r"(a0), "r"(a1), "r"(a2), "r"(a3), "r"(b0), "r"(b1))

#define ONES2 0x3F803F80u   // bf16x2 {1.0, 1.0}

__device__ float g_partial[S_MC * BATCH * F2];
__device__ int   g_count;

__device__ __forceinline__ float tanh_fast(float x) {
    float y;
    asm("tanh.approx.f32 %0, %1;" : "=f"(y) : "f"(x));
    return y;
}
__device__ __forceinline__ float elu_f(float x) {
    return x > 0.0f ? x : (__expf(x) - 1.0f);
}
__device__ __forceinline__ float tf32r(float x) {
    unsigned u; CVT_TF32(u, x); return __uint_as_float(u);
}

__global__ void __launch_bounds__(NTH, 1)
gat_fused_kernel(const float* __restrict__ x,
                 const float* __restrict__ emb,
                 const int*   __restrict__ adj,
                 const float* __restrict__ w1,
                 const float* __restrict__ a_src1,
                 const float* __restrict__ a_dst1,
                 const float* __restrict__ b1,
                 const float* __restrict__ w2,
                 const float* __restrict__ a_src2,
                 const float* __restrict__ a_dst2,
                 const float* __restrict__ b2,
                 float* __restrict__ out)
{
    extern __shared__ float sm[];
    float*    sX    = sm + OFF_X;
    float*    sW    = sm + OFF_W;
    unsigned* sHB   = (unsigned*)(sm + OFF_HB);   // bf16x2 h [c][pair], stride HBD
    unsigned* sMB   = (unsigned*)(sm + OFF_MB);   // bf16x2 mask [i][pair], stride HBD
    float*    sP1S  = sm + OFF_P1S;
    float*    sP1D  = sm + OFF_P1D;
    float*    sB1   = sm + OFF_B1;
    float*    sW2T  = sm + OFF_W2T;
    float*    sH2   = sm + OFF_H2;
    float*    sDST2 = sm + OFF_DST2;
    float*    sMISC = sm + OFF_MISC;
    __shared__ int sLast;

    const int tid = threadIdx.x;
    const int sb  = blockIdx.x;
    const int s   = sb >> 7;
    const int b   = sb & 127;
    const int warp = tid >> 5, lane = tid & 31;
    const int g = lane >> 2, l3 = lane & 3;

    // ---- stage x0 = concat(x[b], emb[b]), rounded to tf32 ----
    {
        const float4* xv = (const float4*)(x   + (size_t)b * NN * F0);
        const float4* ev = (const float4*)(emb + (size_t)b * NN * EMBD);
        for (int i = tid; i < NN * 32; i += NTH) {
            int n = i >> 5, c4 = i & 31;
            float4 v = (c4 < 16) ? xv[n * 16 + c4] : ev[n * 16 + (c4 - 16)];
            v.x = tf32r(v.x); v.y = tf32r(v.y); v.z = tf32r(v.z); v.w = tf32r(v.w);
            *(float4*)&sX[n * SD + c4 * 4] = v;
        }
    }
    // ---- stage W1[s] transposed (tf32): sW[c][f] ----
    {
        const float4* wv = (const float4*)(w1 + (size_t)s * H1 * 128 * F1);
        for (int i = tid; i < 4096; i += NTH) {
            int head = i >> 9;
            int rem  = i & 511;
            int f = rem >> 2, o4 = rem & 3;
            float4 v = wv[i];
            int c = head * 16 + o4 * 4;
            sW[(c + 0) * SD + f] = tf32r(v.x);
            sW[(c + 1) * SD + f] = tf32r(v.y);
            sW[(c + 2) * SD + f] = tf32r(v.z);
            sW[(c + 3) * SD + f] = tf32r(v.w);
        }
    }
    // ---- adjacency mask as packed bf16x2 {1.0/0.0} per j-pair ----
    {
        const int2* arow = (const int2*)(adj + (size_t)b * NN * NN);
        for (int idx = tid; idx < 128 * 64; idx += NTH) {
            int i = idx >> 6, p = idx & 63;
            int2 av = arow[i * 64 + p];
            unsigned w = (av.x ? 0x3F80u : 0u) | (av.y ? 0x3F800000u : 0u);
            sMB[i * HBD + p] = w;
        }
    }
    // ---- small params ----
    if (tid < 128) { sP1S[tid] = a_src1[s * 128 + tid]; sP1D[tid] = a_dst1[s * 128 + tid]; }
    if (tid < 16)  sB1[tid] = b1[tid];
    if (tid < 256) { int f = tid >> 1, o = tid & 1; sW2T[o * 128 + f] = w2[s * 256 + tid]; }
    if (tid == 0) {
        sMISC[0] = a_src2[s * 2 + 0]; sMISC[1] = a_src2[s * 2 + 1];
        sMISC[2] = a_dst2[s * 2 + 0]; sMISC[3] = a_dst2[s * 2 + 1];
        sMISC[4] = b2[0];             sMISC[5] = b2[1];
    }
    __syncthreads();

    // ---- GEMM1 (tf32 tensor): h[c][n]; epilogue packs h to bf16x2 [c][n-pair] ----
    {
        const int ct = (warp >> 2) * 16;
        const int ra = ct + g, rb = ra + 8;
        const float* wra = sW + ra * SD;
        const float* wrb = sW + rb * SD;
#pragma unroll
        for (int q = 0; q < 4; q++) {
            const int n0 = ((warp & 3) + 4 * q) * 8;
            const float* xb = sX + (n0 + g) * SD;
            float c0 = 0.f, c1 = 0.f, c2 = 0.f, c3 = 0.f;
#pragma unroll
            for (int t = 0; t < 8; t++) {
                const int o = 16 * t + 4 * l3;
                const float4 A0 = *(const float4*)&wra[o];
                const float4 A1 = *(const float4*)&wrb[o];
                const float4 Bv = *(const float4*)&xb[o];
                MMA_TF32(c0, c1, c2, c3,
                         __float_as_uint(A0.x), __float_as_uint(A1.x),
                         __float_as_uint(A0.y), __float_as_uint(A1.y),
                         __float_as_uint(Bv.x), __float_as_uint(Bv.y));
                MMA_TF32(c0, c1, c2, c3,
                         __float_as_uint(A0.z), __float_as_uint(A1.z),
                         __float_as_uint(A0.w), __float_as_uint(A1.w),
                         __float_as_uint(Bv.z), __float_as_uint(Bv.w));
            }
            // c0,c1 = h[ra][n0+2l3, +1]; c2,c3 = h[rb][...]. Pack consecutive n.
            unsigned wa, wb;
            PACKBF(wa, c1, c0);
            PACKBF(wb, c3, c2);
            sHB[ra * HBD + (n0 >> 1) + l3] = wa;
            sHB[rb * HBD + (n0 >> 1) + l3] = wb;
        }
    }
    __syncthreads();

    // ---- att projections from bf16 h -> packed exp factors ----
    {
        const int head = tid >> 7, n = tid & 127;
        const unsigned* hw = sHB + (head * 16) * HBD + (n >> 1);
        const int amt = (1 - (n & 1)) * 16;
        float sa = 0.0f, da = 0.0f;
#pragma unroll
        for (int o = 0; o < 16; o++) {
            unsigned w = hw[o * HBD];
            float t = tanh_fast(__uint_as_float((w << amt) & 0xFFFF0000u));
            sa += t * sP1S[head * 16 + o];
            da += t * sP1D[head * 16 + o];
        }
        float ed  = __expf(da);
        float ed2 = __expf(0.2f * da);
        float edn  = __shfl_down_sync(0xffffffffu, ed, 1);
        float ed2n = __shfl_down_sync(0xffffffffu, ed2, 1);
        unsigned* EPB  = (unsigned*)(sX + OFF_EPB);
        unsigned* EP2B = (unsigned*)(sX + OFF_EP2B);
        if (!(n & 1)) {
            unsigned w1p, w2p;
            PACKBF(w1p, edn, ed);
            PACKBF(w2p, ed2n, ed2);
            EPB[head * 64 + (n >> 1)]  = w1p;
            EP2B[head * 64 + (n >> 1)] = w2p;
        }
        float2* SP = (float2*)(sX + OFF_SP);
        SP[tid] = make_float2(__expf(sa), __expf(0.2f * sa));
    }
    __syncthreads();

    // ---- flash-style AV: 64 jobs, bf16 m16n8k16 mma; row sums via ones-MMA ----
    {
        const unsigned* EPBb  = (const unsigned*)(sX + OFF_EPB);
        const unsigned* EP2Bb = (const unsigned*)(sX + OFF_EP2B);
        const float2*   SP    = (const float2*)(sX + OFF_SP);
        for (int job = warp; job < 64; job += 32) {
            const int head = job >> 3, rt = job & 7;
            const int i0 = rt * 16;
            const int ra = i0 + g, rb = ra + 8;
            const float2 spaf = SP[head * 128 + ra];
            const float2 spbf = SP[head * 128 + rb];
            unsigned EsA, Es2A, EsB, Es2B;
            PACKBF(EsA,  spaf.x, spaf.x);
            PACKBF(Es2A, spaf.y, spaf.y);
            PACKBF(EsB,  spbf.x, spbf.x);
            PACKBF(Es2B, spbf.y, spbf.y);
            float cA0 = 0.f, cA1 = 0.f, cA2 = 0.f, cA3 = 0.f;
            float cB0 = 0.f, cB1 = 0.f, cB2 = 0.f, cB3 = 0.f;
            float cS0 = 0.f, cS1 = 0.f, cS2 = 0.f, cS3 = 0.f;
            const unsigned* EPh  = EPBb + head * 64;
            const unsigned* EP2h = EP2Bb + head * 64;
            const unsigned* MA = sMB + ra * HBD;
            const unsigned* MBp = sMB + rb * HBD;
            const unsigned* H0 = sHB + (head * 16 + g) * HBD;
            const unsigned* H1p = sHB + (head * 16 + 8 + g) * HBD;
#pragma unroll
            for (int t = 0; t < 8; t++) {
                const int p0 = 8 * t + l3, p1 = p0 + 4;
                const unsigned eb0 = EPh[p0],  eb1 = EPh[p1];
                const unsigned e20 = EP2h[p0], e21 = EP2h[p1];
                const unsigned ma0 = MA[p0],  ma1 = MA[p1];
                const unsigned mb0 = MBp[p0], mb1 = MBp[p1];
                unsigned t0, t1, a0, a1, a2, a3;
                HMUL2B(t0, EsA, eb0); HMUL2B(t1, Es2A, e20);
                HMAX2B(a0, t0, t1);   HMUL2B(a0, a0, ma0);
                HMUL2B(t0, EsB, eb0); HMUL2B(t1, Es2B, e20);
                HMAX2B(a1, t0, t1);   HMUL2B(a1, a1, mb0);
                HMUL2B(t0, EsA, eb1); HMUL2B(t1, Es2A, e21);
                HMAX2B(a2, t0, t1);   HMUL2B(a2, a2, ma1);
                HMUL2B(t0, EsB, eb1); HMUL2B(t1, Es2B, e21);
                HMAX2B(a3, t0, t1);   HMUL2B(a3, a3, mb1);
                const unsigned h00 = H0[p0], h01 = H0[p1];
                const unsigned h10 = H1p[p0], h11 = H1p[p1];
                MMA_BF16(cA0, cA1, cA2, cA3, a0, a1, a2, a3, h00, h01);
                MMA_BF16(cB0, cB1, cB2, cB3, a0, a1, a2, a3, h10, h11);
                MMA_BF16(cS0, cS1, cS2, cS3, a0, a1, a2, a3, ONES2, ONES2);
            }
            const float inva = 1.0f / cS0;     // row sum of ra (all ones-cols equal)
            const float invb = 1.0f / cS2;     // row sum of rb
            const int cl0 = l3 * 2;
            const float bi00 = sB1[cl0], bi01 = sB1[cl0 + 1];
            const float bi10 = sB1[cl0 + 8], bi11 = sB1[cl0 + 9];
            const int c0c = head * 16;
            *(float2*)&sW[ra * SD + c0c + cl0] =
                make_float2(elu_f(cA0 * inva + bi00), elu_f(cA1 * inva + bi01));
            *(float2*)&sW[ra * SD + c0c + 8 + cl0] =
                make_float2(elu_f(cB0 * inva + bi10), elu_f(cB1 * inva + bi11));
            *(float2*)&sW[rb * SD + c0c + cl0] =
                make_float2(elu_f(cA2 * invb + bi00), elu_f(cA3 * invb + bi01));
            *(float2*)&sW[rb * SD + c0c + 8 + cl0] =
                make_float2(elu_f(cB2 * invb + bi10), elu_f(cB3 * invb + bi11));
        }
    }
    __syncthreads();

    // ---- layer 2 linear: h2[n][0:2], f split 8 ways + shfl reduce ----
    {
        const int n = tid >> 3, fs = tid & 7;
        const float* xr = sW + n * SD + fs * 16;
        const ull* w2o0 = (const ull*)&sW2T[0 * 128 + fs * 16];
        const ull* w2o1 = (const ull*)&sW2T[1 * 128 + fs * 16];
        ull acc0 = 0ULL, acc1 = 0ULL;
#pragma unroll
        for (int fp = 0; fp < 8; fp++) {
            const ull xp = *(const ull*)&xr[fp * 2];
            FFMA2(acc0, xp, w2o0[fp], acc0);
            FFMA2(acc1, xp, w2o1[fp], acc1);
        }
        float l0, h0, l1, h1;
        UNPK2(l0, h0, acc0); UNPK2(l1, h1, acc1);
        float p0 = l0 + h0, p1 = l1 + h1;
#pragma unroll
        for (int d = 4; d > 0; d >>= 1) {
            p0 += __shfl_xor_sync(0xffffffffu, p0, d);
            p1 += __shfl_xor_sync(0xffffffffu, p1, d);
        }
        if (fs == 0) { sH2[2 * n] = p0; sH2[2 * n + 1] = p1; }
    }
    __syncthreads();
    if (tid < 128) {
        int n = tid;
        float t0 = tanh_fast(sH2[2 * n]);
        float t1 = tanh_fast(sH2[2 * n + 1]);
        sDST2[n] = t0 * sMISC[2] + t1 * sMISC[3];
        if (n == 127) sMISC[6] = t0 * sMISC[0] + t1 * sMISC[1];
    }
    __syncthreads();

    // ---- ego-node attention row (i=127): mask-multiplied exp, AV, log_softmax ----
    if (tid < 32) {
        float src = sMISC[6];
        float sum = 0.0f, a0 = 0.0f, a1 = 0.0f;
        const int amt = (1 - (lane & 1)) * 16;
#pragma unroll
        for (int gg = 0; gg < 4; gg++) {
            int j = gg * 32 + lane;
            float v = src + sDST2[j];
            v = fmaxf(v, 0.2f * v);
            unsigned mw = sMB[127 * HBD + (j >> 1)];
            float mf = __uint_as_float((mw << amt) & 0xFFFF0000u);  // 1.0f or 0.0f
            float e = __expf(v) * mf;
            sum += e;
            a0 += e * sH2[2 * j];
            a1 += e * sH2[2 * j + 1];
        }
#pragma unroll
        for (int d = 16; d > 0; d >>= 1) {
            sum += __shfl_xor_sync(0xffffffffu, sum, d);
            a0  += __shfl_xor_sync(0xffffffffu, a0, d);
            a1  += __shfl_xor_sync(0xffffffffu, a1, d);
        }
        if (lane == 0) {
            float inv = 1.0f / sum;
            float o0 = a0 * inv + sMISC[4];
            float o1 = a1 * inv + sMISC[5];
            float mm  = fmaxf(o0, o1);
            float lse = mm + logf(expf(o0 - mm) + expf(o1 - mm));
            g_partial[(s * BATCH + b) * 2 + 0] = o0 - lse;
            g_partial[(s * BATCH + b) * 2 + 1] = o1 - lse;
        }
    }

    // ---- last-CTA final reduce (mean over S) ----
    if (tid == 0) {
        __threadfence();
        int old = atomicAdd(&g_count, 1);
        sLast = (old == (S_MC * BATCH - 1)) ? 1 : 0;
    }
    __syncthreads();
    if (sLast) {
        if (tid < 256) {
            const volatile float* gp = g_partial;
            float v = gp[tid] + gp[256 + tid] + gp[512 + tid] + gp[768 + tid];
            out[tid] = 0.25f * v;
        }
        if (tid == 0) g_count = 0;
    }
}

extern "C" void kernel_launch(void* const* d_in, const int* in_sizes, int n_in,
                              void* d_out, int out_size)
{
    const float* x      = (const float*)d_in[0];
    const float* emb    = (const float*)d_in[1];
    const int*   adj    = (const int*)d_in[2];
    const float* w1     = (const float*)d_in[3];
    const float* a_src1 = (const float*)d_in[4];
    const float* a_dst1 = (const float*)d_in[5];
    const float* b1     = (const float*)d_in[6];
    const float* w2     = (const float*)d_in[7];
    const float* a_src2 = (const float*)d_in[8];
    const float* a_dst2 = (const float*)d_in[9];
    const float* b2     = (const float*)d_in[10];

    cudaFuncSetAttribute(gat_fused_kernel,
                         cudaFuncAttributeMaxDynamicSharedMemorySize, SMEM_BYTES);

    gat_fused_kernel<<<S_MC * BATCH, NTH, SMEM_BYTES>>>(
        x, emb, adj, w1, a_src1, a_dst1, b1, w2, a_src2, a_dst2, b2,
        (float*)d_out);
}

// round 13
// speedup vs baseline: 4.5826x; 1.1628x over previous
#include <cuda_runtime.h>
#include <cuda_bf16.h>
#include <math.h>

// Problem constants
#define S_MC   4
#define BATCH  128
#define NN     128
#define F0     64
#define EMBD   64
#define H1     8
#define F1     16
#define F2     2

#define NTH    1024
#define SD     144   // stride for sX/sW fp32 tiles: conflict-free m16n8k8-style lds.128
#define HBD    68    // stride (32-bit words) for hB / maskb: addr%32 = 4g+l3 -> conflict-free

// SMEM layout (32-bit word offsets)
#define OFF_X     0          // 18432: x0 fp32 during GEMM1; then EPB/EP2B/SP
#define OFF_W     18432      // 18432: W1^T fp32 -> xs2 fp32
#define OFF_HB    36864      // 8704: h as bf16x2 [c][j-pair], stride 68
#define OFF_MB    45568      // 8704: adj mask as bf16x2 {1.0/0.0} [i][j-pair], stride 68
#define OFF_P1S   54272      // 128
#define OFF_P1D   54400      // 128
#define OFF_B1    54528      // 16
#define OFF_W2T   54544      // 256
#define OFF_H2    54800      // 256
#define OFF_DST2  55056      // 128
#define OFF_MISC  55184      // 16
#define SMEM_FLOATS 55200
#define SMEM_BYTES (SMEM_FLOATS * 4)   // 220800

// sub-offsets inside OFF_X after GEMM1 (x0 dead)
#define OFF_EPB   0          // 512 words: bf16x2 exp(dst) pairs per head
#define OFF_EP2B  512        // 512 words: 0.2-versions
#define OFF_SP    1024       // 2048 floats: float2 {exp(src), exp(0.2 src)} per (head,n)

typedef unsigned long long ull;

#define FFMA2(d, a, b, c) \
    asm("fma.rn.f32x2 %0, %1, %2, %3;" : "=l"(d) : "l"(a), "l"(b), "l"(c))
#define UNPK2(lo, hi, p) \
    asm("mov.b64 {%0, %1}, %2;" : "=f"(lo), "=f"(hi) : "l"(p))
#define CVT_TF32(u, f) \
    asm("cvt.rna.tf32.f32 %0, %1;" : "=r"(u) : "f"(f))
#define PACKBF(d, hi, lo) \
    asm("cvt.rn.bf16x2.f32 %0, %1, %2;" : "=r"(d) : "f"(hi), "f"(lo))
#define HMUL2B(d, a, b) \
    asm("mul.bf16x2 %0, %1, %2;" : "=r"(d) : "r"(a), "r"(b))
#define HMAX2B(d, a, b) \
    asm("max.bf16x2 %0, %1, %2;" : "=r"(d) : "r"(a), "r"(b))
#define MMA_TF32(c0, c1, c2, c3, a0, a1, a2, a3, b0, b1) \
    asm("mma.sync.aligned.m16n8k8.row.col.f32.tf32.tf32.f32 " \
        "{%0,%1,%2,%3}, {%4,%5,%6,%7}, {%8,%9}, {%0,%1,%2,%3};" \
        : "+f"(c0), "+f"(c1), "+f"(c2), "+f"(c3) \
        : "r"(a0), "r"(a1), "r"(a2), "r"(a3), "r"(b0), "r"(b1))
#define MMA_BF16(c0, c1, c2, c3, a0, a1, a2, a3, b0, b1) \
    asm("mma.sync.aligned.m16n8k16.row.col.f32.bf16.bf16.f32 " \
        "{%0,%1,%2,%3}, {%4,%5,%6,%7}, {%8,%9}, {%0,%1,%2,%3};" \
        : "+f"(c0), "+f"(c1), "+f"(c2), "+f"(c3) \
        : "r"(a0), "r"(a1), "r"(a2), "r"(a3), "r"(b0), "r"(b1))

#define ONES2 0x3F803F80u   // bf16x2 {1.0, 1.0}

__device__ float g_partial[S_MC * BATCH * F2];
__device__ int   g_count;

__device__ __forceinline__ float tanh_fast(float x) {
    float y;
    asm("tanh.approx.f32 %0, %1;" : "=f"(y) : "f"(x));
    return y;
}
__device__ __forceinline__ float elu_f(float x) {
    return x > 0.0f ? x : (__expf(x) - 1.0f);
}
__device__ __forceinline__ float tf32r(float x) {
    unsigned u; CVT_TF32(u, x); return __uint_as_float(u);
}

__global__ void __launch_bounds__(NTH, 1)
gat_fused_kernel(const float* __restrict__ x,
                 const float* __restrict__ emb,
                 const int*   __restrict__ adj,
                 const float* __restrict__ w1,
                 const float* __restrict__ a_src1,
                 const float* __restrict__ a_dst1,
                 const float* __restrict__ b1,
                 const float* __restrict__ w2,
                 const float* __restrict__ a_src2,
                 const float* __restrict__ a_dst2,
                 const float* __restrict__ b2,
                 float* __restrict__ out)
{
    extern __shared__ float sm[];
    float*    sX    = sm + OFF_X;
    float*    sW    = sm + OFF_W;
    unsigned* sHB   = (unsigned*)(sm + OFF_HB);
    unsigned* sMB   = (unsigned*)(sm + OFF_MB);
    float*    sP1S  = sm + OFF_P1S;
    float*    sP1D  = sm + OFF_P1D;
    float*    sB1   = sm + OFF_B1;
    float*    sW2T  = sm + OFF_W2T;
    float*    sH2   = sm + OFF_H2;
    float*    sDST2 = sm + OFF_DST2;
    float*    sMISC = sm + OFF_MISC;
    __shared__ int sLast;

    const int tid = threadIdx.x;
    const int sb  = blockIdx.x;
    const int s   = sb >> 7;
    const int b   = sb & 127;
    const int warp = tid >> 5, lane = tid & 31;
    const int g = lane >> 2, l3 = lane & 3;

    // ---- stage x0 = concat(x[b], emb[b]), rounded to tf32 ----
    {
        const float4* xv = (const float4*)(x   + (size_t)b * NN * F0);
        const float4* ev = (const float4*)(emb + (size_t)b * NN * EMBD);
        for (int i = tid; i < NN * 32; i += NTH) {
            int n = i >> 5, c4 = i & 31;
            float4 v = (c4 < 16) ? xv[n * 16 + c4] : ev[n * 16 + (c4 - 16)];
            v.x = tf32r(v.x); v.y = tf32r(v.y); v.z = tf32r(v.z); v.w = tf32r(v.w);
            *(float4*)&sX[n * SD + c4 * 4] = v;
        }
    }
    // ---- stage W1[s] transposed (tf32): sW[c][f] ----
    {
        const float4* wv = (const float4*)(w1 + (size_t)s * H1 * 128 * F1);
        for (int i = tid; i < 4096; i += NTH) {
            int head = i >> 9;
            int rem  = i & 511;
            int f = rem >> 2, o4 = rem & 3;
            float4 v = wv[i];
            int c = head * 16 + o4 * 4;
            sW[(c + 0) * SD + f] = tf32r(v.x);
            sW[(c + 1) * SD + f] = tf32r(v.y);
            sW[(c + 2) * SD + f] = tf32r(v.z);
            sW[(c + 3) * SD + f] = tf32r(v.w);
        }
    }
    // ---- adjacency mask as packed bf16x2 {1.0/0.0} per j-pair ----
    {
        const int2* arow = (const int2*)(adj + (size_t)b * NN * NN);
        for (int idx = tid; idx < 128 * 64; idx += NTH) {
            int i = idx >> 6, p = idx & 63;
            int2 av = arow[i * 64 + p];
            unsigned w = (av.x ? 0x3F80u : 0u) | (av.y ? 0x3F800000u : 0u);
            sMB[i * HBD + p] = w;
        }
    }
    // ---- small params ----
    if (tid < 128) { sP1S[tid] = a_src1[s * 128 + tid]; sP1D[tid] = a_dst1[s * 128 + tid]; }
    if (tid < 16)  sB1[tid] = b1[tid];
    if (tid < 256) { int f = tid >> 1, o = tid & 1; sW2T[o * 128 + f] = w2[s * 256 + tid]; }
    if (tid == 0) {
        sMISC[0] = a_src2[s * 2 + 0]; sMISC[1] = a_src2[s * 2 + 1];
        sMISC[2] = a_dst2[s * 2 + 0]; sMISC[3] = a_dst2[s * 2 + 1];
        sMISC[4] = b2[0];             sMISC[5] = b2[1];
    }
    __syncthreads();

    // ---- GEMM1 (tf32 tensor), k-outer: A-fragments loaded ONCE per k-chunk ----
    {
        const int ct = (warp >> 2) * 16;
        const int ra = ct + g, rb = ra + 8;
        const float* wra = sW + ra * SD;
        const float* wrb = sW + rb * SD;
        const int nbase = (warp & 3) * 8;
        float acc[4][4];
#pragma unroll
        for (int q = 0; q < 4; q++)
#pragma unroll
            for (int c = 0; c < 4; c++) acc[q][c] = 0.f;

#pragma unroll
        for (int t = 0; t < 8; t++) {
            const int o = 16 * t + 4 * l3;
            const float4 A0 = *(const float4*)&wra[o];
            const float4 A1 = *(const float4*)&wrb[o];
#pragma unroll
            for (int q = 0; q < 4; q++) {
                const int n0 = nbase + 32 * q;
                const float4 Bv = *(const float4*)&sX[(n0 + g) * SD + o];
                MMA_TF32(acc[q][0], acc[q][1], acc[q][2], acc[q][3],
                         __float_as_uint(A0.x), __float_as_uint(A1.x),
                         __float_as_uint(A0.y), __float_as_uint(A1.y),
                         __float_as_uint(Bv.x), __float_as_uint(Bv.y));
                MMA_TF32(acc[q][0], acc[q][1], acc[q][2], acc[q][3],
                         __float_as_uint(A0.z), __float_as_uint(A1.z),
                         __float_as_uint(A0.w), __float_as_uint(A1.w),
                         __float_as_uint(Bv.z), __float_as_uint(Bv.w));
            }
        }
#pragma unroll
        for (int q = 0; q < 4; q++) {
            const int n0 = nbase + 32 * q;
            unsigned wa, wb;
            PACKBF(wa, acc[q][1], acc[q][0]);
            PACKBF(wb, acc[q][3], acc[q][2]);
            sHB[ra * HBD + (n0 >> 1) + l3] = wa;
            sHB[rb * HBD + (n0 >> 1) + l3] = wb;
        }
    }
    __syncthreads();

    // ---- att projections from bf16 h -> packed exp factors ----
    {
        const int head = tid >> 7, n = tid & 127;
        const unsigned* hw = sHB + (head * 16) * HBD + (n >> 1);
        const int amt = (1 - (n & 1)) * 16;
        float sa = 0.0f, da = 0.0f;
#pragma unroll
        for (int o = 0; o < 16; o++) {
            unsigned w = hw[o * HBD];
            float t = tanh_fast(__uint_as_float((w << amt) & 0xFFFF0000u));
            sa += t * sP1S[head * 16 + o];
            da += t * sP1D[head * 16 + o];
        }
        float ed  = __expf(da);
        float ed2 = __expf(0.2f * da);
        float edn  = __shfl_down_sync(0xffffffffu, ed, 1);
        float ed2n = __shfl_down_sync(0xffffffffu, ed2, 1);
        unsigned* EPB  = (unsigned*)(sX + OFF_EPB);
        unsigned* EP2B = (unsigned*)(sX + OFF_EP2B);
        if (!(n & 1)) {
            unsigned w1p, w2p;
            PACKBF(w1p, edn, ed);
            PACKBF(w2p, ed2n, ed2);
            EPB[head * 64 + (n >> 1)]  = w1p;
            EP2B[head * 64 + (n >> 1)] = w2p;
        }
        float2* SP = (float2*)(sX + OFF_SP);
        SP[tid] = make_float2(__expf(sa), __expf(0.2f * sa));
    }
    __syncthreads();

    // ---- flash-style AV: 64 jobs, bf16 m16n8k16 mma; row sums via ones-MMA ----
    {
        const unsigned* EPBb  = (const unsigned*)(sX + OFF_EPB);
        const unsigned* EP2Bb = (const unsigned*)(sX + OFF_EP2B);
        const float2*   SP    = (const float2*)(sX + OFF_SP);
        for (int job = warp; job < 64; job += 32) {
            const int head = job >> 3, rt = job & 7;
            const int i0 = rt * 16;
            const int ra = i0 + g, rb = ra + 8;
            const float2 spaf = SP[head * 128 + ra];
            const float2 spbf = SP[head * 128 + rb];
            unsigned EsA, Es2A, EsB, Es2B;
            PACKBF(EsA,  spaf.x, spaf.x);
            PACKBF(Es2A, spaf.y, spaf.y);
            PACKBF(EsB,  spbf.x, spbf.x);
            PACKBF(Es2B, spbf.y, spbf.y);
            float cA0 = 0.f, cA1 = 0.f, cA2 = 0.f, cA3 = 0.f;
            float cB0 = 0.f, cB1 = 0.f, cB2 = 0.f, cB3 = 0.f;
            float cS0 = 0.f, cS1 = 0.f, cS2 = 0.f, cS3 = 0.f;
            const unsigned* EPh  = EPBb + head * 64;
            const unsigned* EP2h = EP2Bb + head * 64;
            const unsigned* MA = sMB + ra * HBD;
            const unsigned* MBp = sMB + rb * HBD;
            const unsigned* H0 = sHB + (head * 16 + g) * HBD;
            const unsigned* H1p = sHB + (head * 16 + 8 + g) * HBD;
#pragma unroll
            for (int t = 0; t < 8; t++) {
                const int p0 = 8 * t + l3, p1 = p0 + 4;
                const unsigned eb0 = EPh[p0],  eb1 = EPh[p1];
                const unsigned e20 = EP2h[p0], e21 = EP2h[p1];
                const unsigned ma0 = MA[p0],  ma1 = MA[p1];
                const unsigned mb0 = MBp[p0], mb1 = MBp[p1];
                unsigned t0, t1, a0, a1, a2, a3;
                HMUL2B(t0, EsA, eb0); HMUL2B(t1, Es2A, e20);
                HMAX2B(a0, t0, t1);   HMUL2B(a0, a0, ma0);
                HMUL2B(t0, EsB, eb0); HMUL2B(t1, Es2B, e20);
                HMAX2B(a1, t0, t1);   HMUL2B(a1, a1, mb0);
                HMUL2B(t0, EsA, eb1); HMUL2B(t1, Es2A, e21);
                HMAX2B(a2, t0, t1);   HMUL2B(a2, a2, ma1);
                HMUL2B(t0, EsB, eb1); HMUL2B(t1, Es2B, e21);
                HMAX2B(a3, t0, t1);   HMUL2B(a3, a3, mb1);
                const unsigned h00 = H0[p0], h01 = H0[p1];
                const unsigned h10 = H1p[p0], h11 = H1p[p1];
                MMA_BF16(cA0, cA1, cA2, cA3, a0, a1, a2, a3, h00, h01);
                MMA_BF16(cB0, cB1, cB2, cB3, a0, a1, a2, a3, h10, h11);
                MMA_BF16(cS0, cS1, cS2, cS3, a0, a1, a2, a3, ONES2, ONES2);
            }
            const float inva = 1.0f / cS0;
            const float invb = 1.0f / cS2;
            const int cl0 = l3 * 2;
            const float bi00 = sB1[cl0], bi01 = sB1[cl0 + 1];
            const float bi10 = sB1[cl0 + 8], bi11 = sB1[cl0 + 9];
            const int c0c = head * 16;
            *(float2*)&sW[ra * SD + c0c + cl0] =
                make_float2(elu_f(cA0 * inva + bi00), elu_f(cA1 * inva + bi01));
            *(float2*)&sW[ra * SD + c0c + 8 + cl0] =
                make_float2(elu_f(cB0 * inva + bi10), elu_f(cB1 * inva + bi11));
            *(float2*)&sW[rb * SD + c0c + cl0] =
                make_float2(elu_f(cA2 * invb + bi00), elu_f(cA3 * invb + bi01));
            *(float2*)&sW[rb * SD + c0c + 8 + cl0] =
                make_float2(elu_f(cB2 * invb + bi10), elu_f(cB3 * invb + bi11));
        }
    }
    __syncthreads();

    // ---- layer 2 linear: h2[n][0:2], f split 8 ways + shfl reduce ----
    {
        const int n = tid >> 3, fs = tid & 7;
        const float* xr = sW + n * SD + fs * 16;
        const ull* w2o0 = (const ull*)&sW2T[0 * 128 + fs * 16];
        const ull* w2o1 = (const ull*)&sW2T[1 * 128 + fs * 16];
        ull acc0 = 0ULL, acc1 = 0ULL;
#pragma unroll
        for (int fp = 0; fp < 8; fp++) {
            const ull xp = *(const ull*)&xr[fp * 2];
            FFMA2(acc0, xp, w2o0[fp], acc0);
            FFMA2(acc1, xp, w2o1[fp], acc1);
        }
        float l0, h0, l1, h1;
        UNPK2(l0, h0, acc0); UNPK2(l1, h1, acc1);
        float p0 = l0 + h0, p1 = l1 + h1;
#pragma unroll
        for (int d = 4; d > 0; d >>= 1) {
            p0 += __shfl_xor_sync(0xffffffffu, p0, d);
            p1 += __shfl_xor_sync(0xffffffffu, p1, d);
        }
        if (fs == 0) { sH2[2 * n] = p0; sH2[2 * n + 1] = p1; }
    }
    __syncthreads();
    if (tid < 128) {
        int n = tid;
        float t0 = tanh_fast(sH2[2 * n]);
        float t1 = tanh_fast(sH2[2 * n + 1]);
        sDST2[n] = t0 * sMISC[2] + t1 * sMISC[3];
        if (n == 127) sMISC[6] = t0 * sMISC[0] + t1 * sMISC[1];
    }
    __syncthreads();

    // ---- ego-node attention row (i=127): mask-multiplied exp, AV, log_softmax ----
    if (tid < 32) {
        float src = sMISC[6];
        float sum = 0.0f, a0 = 0.0f, a1 = 0.0f;
        const int amt = (1 - (lane & 1)) * 16;
#pragma unroll
        for (int gg = 0; gg < 4; gg++) {
            int j = gg * 32 + lane;
            float v = src + sDST2[j];
            v = fmaxf(v, 0.2f * v);
            unsigned mw = sMB[127 * HBD + (j >> 1)];
            float mf = __uint_as_float((mw << amt) & 0xFFFF0000u);
            float e = __expf(v) * mf;
            sum += e;
            a0 += e * sH2[2 * j];
            a1 += e * sH2[2 * j + 1];
        }
#pragma unroll
        for (int d = 16; d > 0; d >>= 1) {
            sum += __shfl_xor_sync(0xffffffffu, sum, d);
            a0  += __shfl_xor_sync(0xffffffffu, a0, d);
            a1  += __shfl_xor_sync(0xffffffffu, a1, d);
        }
        if (lane == 0) {
            float inv = 1.0f / sum;
            float o0 = a0 * inv + sMISC[4];
            float o1 = a1 * inv + sMISC[5];
            float mm  = fmaxf(o0, o1);
            float lse = mm + logf(expf(o0 - mm) + expf(o1 - mm));
            g_partial[(s * BATCH + b) * 2 + 0] = o0 - lse;
            g_partial[(s * BATCH + b) * 2 + 1] = o1 - lse;
        }
    }

    // ---- last-CTA final reduce (mean over S) ----
    if (tid == 0) {
        __threadfence();
        int old = atomicAdd(&g_count, 1);
        sLast = (old == (S_MC * BATCH - 1)) ? 1 : 0;
    }
    __syncthreads();
    if (sLast) {
        if (tid < 256) {
            const volatile float* gp = g_partial;
            float v = gp[tid] + gp[256 + tid] + gp[512 + tid] + gp[768 + tid];
            out[tid] = 0.25f * v;
        }
        if (tid == 0) g_count = 0;
    }
}

extern "C" void kernel_launch(void* const* d_in, const int* in_sizes, int n_in,
                              void* d_out, int out_size)
{
    const float* x      = (const float*)d_in[0];
    const float* emb    = (const float*)d_in[1];
    const int*   adj    = (const int*)d_in[2];
    const float* w1     = (const float*)d_in[3];
    const float* a_src1 = (const float*)d_in[4];
    const float* a_dst1 = (const float*)d_in[5];
    const float* b1     = (const float*)d_in[6];
    const float* w2     = (const float*)d_in[7];
    const float* a_src2 = (const float*)d_in[8];
    const float* a_dst2 = (const float*)d_in[9];
    const float* b2     = (const float*)d_in[10];

    cudaFuncSetAttribute(gat_fused_kernel,
                         cudaFuncAttributeMaxDynamicSharedMemorySize, SMEM_BYTES);

    gat_fused_kernel<<<S_MC * BATCH, NTH, SMEM_BYTES>>>(
        x, emb, adj, w1, a_src1, a_dst1, b1, w2, a_src2, a_dst2, b2,
        (float*)d_out);
}